// round 12
// baseline (speedup 1.0000x reference)
#include <cuda_runtime.h>
#include <math.h>

// Problem constants
#define BATCH 32
#define TT 55
#define VV 32000
#define DW 256
#define DD 512
#define AA 200
#define G4 2048   // 4*D
#define NCOL (G4 + AA)   // 2248
#define WTS 2304         // padded row stride of transposed weights

#define NBLK 142           // recurrence blocks
#define NTHR 256
#define NGRP_M 28          // GEMM m-groups (64 rows each, covers 1792 >= 1760)
#define NGRP_N 250         // GEMM n-groups (128 cols each)
#define NGEMM (NGRP_M*NGRP_N)

#define MTILES 112         // m16-tile count (t-major: mt = t*2 + (b>=16))

// Scratch (device globals; no allocation allowed)
__device__ float    g_w4[BATCH*TT*G4];
__device__ float    g_wr[BATCH*TT*AA];
__device__ float    g_h[BATCH*DD];
__device__ float    g_dt[BATCH*AA];
__device__ float    g_gates[BATCH*G4];
__device__ uint4    g_wout_p[(VV/8)*32*32];   // W_out tf32, fragment-permuted
__device__ uint4    g_hall_p[MTILES*64*32];   // h_all tf32, fragment-permuted (t-major)
__device__ float    g_wt[DD*WTS];             // [Wh2h ; Wh2hr] transposed [k][col]
__device__ float    g_wdt[AA*DD];             // Wdc transposed [a][j]
__device__ unsigned g_arrA;
__device__ unsigned g_arrB;

// ---------------------------------------------------------------------------
__device__ __forceinline__ unsigned tf32r(float x) {
    unsigned y;
    asm("cvt.rna.tf32.f32 %0, %1;" : "=r"(y) : "f"(x));
    return y;
}

__global__ void init_kernel(const float* __restrict__ enc) {
    int i = blockIdx.x * blockDim.x + threadIdx.x;
    if (i < BATCH*DD) g_h[i] = enc[i];
    if (i == 0) { g_arrA = 0u; g_arrB = 0u; }
}

__global__ void __launch_bounds__(256) wout_permute(const float* __restrict__ W) {
    int idx = blockIdx.x * blockDim.x + threadIdx.x;
    int lane = idx & 31;
    int sp   = (idx >> 5) & 31;
    int nt   = idx >> 10;
    int g8 = lane >> 2, tq = lane & 3;
    const float* row = W + (size_t)(nt*8 + g8) * DD + sp*16 + tq;
    uint4 o;
    o.x = tf32r(row[0]);
    o.y = tf32r(row[4]);
    o.z = tf32r(row[8]);
    o.w = tf32r(row[12]);
    g_wout_p[idx] = o;
}

// ---- one-time weight transposes -------------------------------------------
__global__ void __launch_bounds__(256) transpose_w(
    const float* __restrict__ Wh2h, const float* __restrict__ Wh2hr)
{
    __shared__ float tile[32][33];
    const int ct = blockIdx.x;
    const int kt = blockIdx.y;
    const int tx = threadIdx.x, ty = threadIdx.y;
    #pragma unroll
    for (int i = 0; i < 4; i++) {
        int col = ct*32 + ty + i*8;
        int k   = kt*32 + tx;
        float v = 0.f;
        if (col < G4)        v = Wh2h[(size_t)col*DD + k];
        else if (col < NCOL) v = Wh2hr[(size_t)(col-G4)*DD + k];
        tile[ty + i*8][tx] = v;
    }
    __syncthreads();
    #pragma unroll
    for (int i = 0; i < 4; i++) {
        int k   = kt*32 + ty + i*8;
        int col = ct*32 + tx;
        g_wt[(size_t)k*WTS + col] = tile[tx][ty + i*8];
    }
}

__global__ void __launch_bounds__(256) transpose_wdc(const float* __restrict__ Wdc)
{
    __shared__ float tile[32][33];
    const int jt = blockIdx.x;
    const int at = blockIdx.y;
    const int tx = threadIdx.x, ty = threadIdx.y;
    #pragma unroll
    for (int i = 0; i < 4; i++) {
        int j = jt*32 + ty + i*8;
        int a = at*32 + tx;
        tile[ty + i*8][tx] = (a < AA) ? Wdc[(size_t)j*AA + a] : 0.f;
    }
    __syncthreads();
    #pragma unroll
    for (int i = 0; i < 4; i++) {
        int a = at*32 + ty + i*8;
        int j = jt*32 + tx;
        if (a < AA) g_wdt[(size_t)a*DD + j] = tile[tx][ty + i*8];
    }
}

__device__ __forceinline__ float sigmoidf_(float x) {
    return 1.f / (1.f + expf(-x));
}

// Fence-free semaphores
__device__ __forceinline__ void sem_arrive(unsigned* ctr) {
    __syncthreads();
    if (threadIdx.x == 0)
        asm volatile("red.release.gpu.global.add.u32 [%0], 1;"
                     :: "l"(ctr) : "memory");
}
__device__ __forceinline__ void sem_wait(unsigned* ctr, unsigned tgt) {
    if (threadIdx.x == 0) {
        unsigned v;
        do {
            asm volatile("ld.acquire.gpu.global.u32 %0, [%1];"
                         : "=r"(v) : "l"(ctr) : "memory");
        } while (v < tgt);
    }
    __syncthreads();
}

__device__ __forceinline__ void mma_tf32(float c[4],
    unsigned a0, unsigned a1, unsigned a2, unsigned a3,
    unsigned b0, unsigned b1)
{
    asm volatile(
        "mma.sync.aligned.m16n8k8.row.col.f32.tf32.tf32.f32 "
        "{%0,%1,%2,%3}, {%4,%5,%6,%7}, {%8,%9}, {%0,%1,%2,%3};\n"
        : "+f"(c[0]), "+f"(c[1]), "+f"(c[2]), "+f"(c[3])
        : "r"(a0), "r"(a1), "r"(a2), "r"(a3), "r"(b0), "r"(b1));
}

// ---------------------------------------------------------------------------
// FUSED persistent kernel:
//   blocks [0,142): recurrence (R11 structure, phase1 reg-resident weights,
//                   b split in two halves of 8 to keep regs < 128).
//                   phase2 stores h directly in mma-fragment order (t-major).
//   blocks [142, 142+NGEMM): output-GEMM CTAs, tile M=64 (t-major) x N=128,
//                   gated on g_arrB step counter; fragment-direct, no smem.
// Co-residency: __launch_bounds__(256,2) -> <=128 regs; 1 recurrence CTA +
// 1 GEMM CTA per SM overlap FMA pipe with TENSOR pipe. If co-residency
// fails, GEMM blocks simply run after the recurrence (still correct).
// ---------------------------------------------------------------------------
__global__ void __launch_bounds__(NTHR, 2) fused_kernel(
    const float* __restrict__ bh2h, const float* __restrict__ bh2hr,
    const float* __restrict__ enc,  const float* __restrict__ act,
    const float* __restrict__ bout, float* __restrict__ out)
{
    extern __shared__ float smem[];

    const int blk  = blockIdx.x;
    const int tid  = threadIdx.x;
    const int w    = tid >> 5;
    const int lane = tid & 31;

    unsigned* arrA; unsigned* arrB;
    asm("cvta.global.u64 %0, g_arrA;" : "=l"(arrA));
    asm("cvta.global.u64 %0, g_arrB;" : "=l"(arrB));

    if (blk < NBLK) {
        // ===================== RECURRENCE PATH =====================
        float* hbuf = smem;           // 8192 floats
        float* part = smem + 8192;    // 4096 floats

        const int colg  = blk >> 1;
        const int bh    = blk & 1;
        const int col   = colg * 32 + lane;
        const int kbase = w * 64;

        // register-resident weights (once)
        float wreg[64];
        #pragma unroll
        for (int i = 0; i < 64; i++)
            wreg[i] = g_wt[(size_t)(kbase + i) * WTS + col];

        // reduction ownership: p0=tid, p1=tid+256
        float biasv[2];
        float dreg[2];
        #pragma unroll
        for (int pi = 0; pi < 2; pi++) {
            int p  = tid + pi * 256;
            int b  = p >> 5;
            int cg = colg * 32 + (p & 31);
            int batch = bh * 16 + b;
            biasv[pi] = 0.f; dreg[pi] = 0.f;
            if (cg < G4) biasv[pi] = bh2h[cg];
            else if (cg < NCOL) {
                biasv[pi] = bh2hr[cg - G4];
                dreg[pi]  = __ldcg(act + batch * AA + (cg - G4));
            }
        }

        // phase2 setup (blocks 0..63)
        const bool p2 = (blk < 64);
        const int  colg2 = blk >> 2;
        const int  b2    = (blk & 3) * 8 + w;
        const int  j2    = colg2 * 32 + lane;
        float creg = 0.f;
        if (p2) creg = __ldcg(enc + b2 * DD + j2);

        // fragment-store index pieces for phase2 h write (fixed except t)
        // m = t*32 + b2 ; mt = t*2 + (b2>>4); g8 = b2&7; r8 = (b2>>3)&1
        unsigned* hp = (unsigned*)g_hall_p;
        const int fs_lane = (b2 & 7) * 4 + (j2 & 3);
        const int fs_comp = ((b2 >> 3) & 1) + 2 * ((j2 >> 2) & 1);
        const int fs_s    = j2 >> 3;
        const int fs_mth  = (b2 >> 4);   // mt = t*2 + fs_mth

        for (int t = 0; t < TT; t++) {
            sem_wait(arrB, 64u * (unsigned)t);

            // stage h rows [bh*16 .. +16) linearly
            {
                const float4* src = (const float4*)(g_h + bh * 16 * DD);
                float4* dst = (float4*)hbuf;
                #pragma unroll
                for (int i = 0; i < 8; i++)
                    dst[i * NTHR + tid] = __ldcg(src + i * NTHR + tid);
            }
            __syncthreads();

            // phase1: two b-halves of 8 (keeps live regs low)
            #pragma unroll
            for (int half = 0; half < 2; half++) {
                float acc[8];
                #pragma unroll
                for (int b = 0; b < 8; b++) acc[b] = 0.f;
                const float* hw = hbuf + kbase + half * 8 * DD;
                #pragma unroll
                for (int k4 = 0; k4 < 64; k4 += 4) {
                    float w0 = wreg[k4], w1 = wreg[k4+1];
                    float w2 = wreg[k4+2], w3 = wreg[k4+3];
                    #pragma unroll
                    for (int b = 0; b < 8; b++) {
                        float4 hv = *(const float4*)(hw + b * DD + k4);
                        acc[b] += w0*hv.x + w1*hv.y + w2*hv.z + w3*hv.w;
                    }
                }
                #pragma unroll
                for (int b = 0; b < 8; b++)
                    part[w * 512 + (half * 8 + b) * 32 + lane] = acc[b];
            }
            __syncthreads();

            // reduce partials, activate, store gates / update dt
            #pragma unroll
            for (int pi = 0; pi < 2; pi++) {
                int p  = tid + pi * 256;
                float s = part[p]          + part[p + 512]
                        + part[p + 1024]   + part[p + 1536]
                        + part[p + 2048]   + part[p + 2560]
                        + part[p + 3072]   + part[p + 3584];
                int b  = p >> 5;
                int cg = colg * 32 + (p & 31);
                int batch = bh * 16 + b;
                if (cg < G4) {
                    float v = g_w4[(size_t)(batch*TT + t) * G4 + cg] + s + biasv[pi];
                    v = (cg < 3*DD) ? sigmoidf_(v) : tanhf(v);
                    g_gates[batch * G4 + cg] = v;
                } else if (cg < NCOL) {
                    int acol = cg - G4;
                    float r = sigmoidf_(g_wr[(size_t)(batch*TT + t) * AA + acol]
                                        + s + biasv[pi]);
                    dreg[pi] *= r;
                    g_dt[batch * AA + acol] = dreg[pi];
                }
            }

            sem_arrive(arrA);

            if (p2) {
                sem_wait(arrA, 142u * (unsigned)(t + 1));

                int bb = (blk & 3) * 8;
                for (int i = tid; i < 8 * AA; i += NTHR)
                    part[i] = __ldcg(g_dt + bb * AA + i);
                __syncthreads();

                const float* wdt = g_wdt + j2;
                const float* dts = part + w * AA;
                float acc_a = 0.f, acc_b = 0.f;
                #pragma unroll 10
                for (int a = 0; a < AA; a += 2) {
                    acc_a += dts[a    ] * wdt[(a    ) * DD];
                    acc_b += dts[a + 1] * wdt[(a + 1) * DD];
                }
                float dtw = tanhf(acc_a + acc_b);
                float gi = __ldcg(g_gates + b2 * G4 + j2);
                float gf = __ldcg(g_gates + b2 * G4 + DD   + j2);
                float go = __ldcg(g_gates + b2 * G4 + 2*DD + j2);
                float ch = __ldcg(g_gates + b2 * G4 + 3*DD + j2);
                creg = gf * creg + gi * ch + dtw;
                float h = go * tanhf(creg);
                g_h[b2 * DD + j2] = h;
                // fragment-order store, t-major m-tiles
                int mt = t * 2 + fs_mth;
                hp[(((size_t)mt * 64 + fs_s) * 32 + fs_lane) * 4 + fs_comp] = tf32r(h);

                sem_arrive(arrB);
            }
        }
    } else {
        // ===================== OUTPUT-GEMM PATH =====================
        const int gb = blk - NBLK;
        const int mg = gb / NGRP_N;          // m-group (64 rows, t-pair pair)
        const int ng = gb % NGRP_N;          // n-group (128 cols)

        // rows [mg*64, mg*64+64) -> t up to 2*mg+1
        int t_need = 2*mg + 1; if (t_need > TT-1) t_need = TT-1;
        sem_wait(arrB, 64u * (unsigned)(t_need + 1));

        const int wmh = (w & 1);             // m half (0/1): 2 m16-tiles each
        const int wnq = (w >> 1);            // n quarter: 4 n8-tiles each
        const int g8  = lane >> 2;
        const int tq  = lane & 3;

        const uint4* aBase = g_hall_p + ((size_t)(mg*4 + wmh*2) * 64) * 32 + lane;
        const uint4* bBase = g_wout_p + ((size_t)(ng*16 + wnq*4) * 32) * 32 + lane;

        float acc[2][4][4];
        #pragma unroll
        for (int mi = 0; mi < 2; mi++)
            #pragma unroll
            for (int ni = 0; ni < 4; ni++)
                #pragma unroll
                for (int q = 0; q < 4; q++) acc[mi][ni][q] = 0.f;

        #pragma unroll 1
        for (int kt = 0; kt < 16; kt++) {
            uint4 bf[4][2];
            #pragma unroll
            for (int ni = 0; ni < 4; ni++) {
                bf[ni][0] = __ldg(bBase + ((size_t)ni * 32 + kt*2    ) * 32);
                bf[ni][1] = __ldg(bBase + ((size_t)ni * 32 + kt*2 + 1) * 32);
            }
            #pragma unroll
            for (int s4 = 0; s4 < 4; s4++) {
                const int s = kt*4 + s4;
                uint4 af[2];
                #pragma unroll
                for (int mi = 0; mi < 2; mi++)
                    af[mi] = __ldcg(aBase + ((size_t)mi * 64 + s) * 32);
                #pragma unroll
                for (int mi = 0; mi < 2; mi++)
                    #pragma unroll
                    for (int ni = 0; ni < 4; ni++) {
                        unsigned b0 = (s4 & 1) ? bf[ni][s4>>1].z : bf[ni][s4>>1].x;
                        unsigned b1 = (s4 & 1) ? bf[ni][s4>>1].w : bf[ni][s4>>1].y;
                        mma_tf32(acc[mi][ni], af[mi].x, af[mi].y, af[mi].z,
                                 af[mi].w, b0, b1);
                    }
            }
        }

        // epilogue: row gm -> (t = gm>>5, b = gm&31) -> out[(b*TT+t)*VV + gn]
        #pragma unroll
        for (int mi = 0; mi < 2; mi++) {
            int gm0 = mg*64 + wmh*32 + mi*16 + g8;
            #pragma unroll
            for (int half = 0; half < 2; half++) {
                int gm = gm0 + half*8;
                int t  = gm >> 5;
                if (t < TT) {
                    int b = gm & 31;
                    float* orow = out + ((size_t)b * TT + t) * VV;
                    #pragma unroll
                    for (int ni = 0; ni < 4; ni++) {
                        int gn = ng*128 + wnq*32 + ni*8 + tq*2;
                        float2 bs = *(const float2*)(bout + gn);
                        float2 o;
                        o.x = acc[mi][ni][half*2    ] + bs.x;
                        o.y = acc[mi][ni][half*2 + 1] + bs.y;
                        *(float2*)(orow + gn) = o;
                    }
                }
            }
        }
    }
}

// ---------------------------------------------------------------------------
// fp32 tiled GEMM (two small precompute GEMMs)
// ---------------------------------------------------------------------------
#define TS 128
#define KT 8

template<bool GATHER>
__global__ void __launch_bounds__(256) gemm_tn(
    int M, int N, int K,
    const float* __restrict__ A, const int* __restrict__ idx,
    const float* __restrict__ B,
    const float* __restrict__ bias,
    float* __restrict__ C, int ldc)
{
    __shared__ float As[KT][TS];
    __shared__ float Bs[KT][TS];

    int tid = threadIdx.x;
    int lrow = tid >> 1;
    int kc   = (tid & 1) * 4;

    int gm_l = blockIdx.y * TS + lrow;
    int gn_l = blockIdx.x * TS + lrow;

    const float* aptr = nullptr;
    if (gm_l < M) {
        int ar = GATHER ? idx[gm_l] : gm_l;
        aptr = A + (size_t)ar * K;
    }
    const float* bptr = (gn_l < N) ? (B + (size_t)gn_l * K) : nullptr;

    int tx = tid & 15;
    int ty = tid >> 4;

    float acc[8][8];
    #pragma unroll
    for (int i = 0; i < 8; i++)
        #pragma unroll
        for (int j = 0; j < 8; j++) acc[i][j] = 0.f;

    for (int k0 = 0; k0 < K; k0 += KT) {
        float4 av = make_float4(0.f, 0.f, 0.f, 0.f);
        float4 bv = make_float4(0.f, 0.f, 0.f, 0.f);
        if (aptr) av = *(const float4*)(aptr + k0 + kc);
        if (bptr) bv = *(const float4*)(bptr + k0 + kc);
        __syncthreads();
        As[kc+0][lrow] = av.x; As[kc+1][lrow] = av.y;
        As[kc+2][lrow] = av.z; As[kc+3][lrow] = av.w;
        Bs[kc+0][lrow] = bv.x; Bs[kc+1][lrow] = bv.y;
        Bs[kc+2][lrow] = bv.z; Bs[kc+3][lrow] = bv.w;
        __syncthreads();
        #pragma unroll
        for (int kk = 0; kk < KT; kk++) {
            float4 a0 = *(const float4*)&As[kk][ty*8];
            float4 a1 = *(const float4*)&As[kk][ty*8+4];
            float4 b0 = *(const float4*)&Bs[kk][tx*8];
            float4 b1 = *(const float4*)&Bs[kk][tx*8+4];
            float a[8] = {a0.x,a0.y,a0.z,a0.w,a1.x,a1.y,a1.z,a1.w};
            float b[8] = {b0.x,b0.y,b0.z,b0.w,b1.x,b1.y,b1.z,b1.w};
            #pragma unroll
            for (int i = 0; i < 8; i++)
                #pragma unroll
                for (int j = 0; j < 8; j++)
                    acc[i][j] += a[i] * b[j];
        }
    }

    #pragma unroll
    for (int i = 0; i < 8; i++) {
        int gm = blockIdx.y * TS + ty*8 + i;
        if (gm < M) {
            #pragma unroll
            for (int j = 0; j < 8; j += 4) {
                int gn = blockIdx.x * TS + tx*8 + j;
                if (gn < N) {
                    float4 bs = *(const float4*)(bias + gn);
                    float4 o;
                    o.x = acc[i][j+0] + bs.x;
                    o.y = acc[i][j+1] + bs.y;
                    o.z = acc[i][j+2] + bs.z;
                    o.w = acc[i][j+3] + bs.w;
                    *(float4*)(C + (size_t)gm * ldc + gn) = o;
                }
            }
        }
    }
}

// ---------------------------------------------------------------------------
// Launch
// ---------------------------------------------------------------------------
extern "C" void kernel_launch(void* const* d_in, const int* in_sizes, int n_in,
                              void* d_out, int out_size) {
    const int*   tgt   = (const int*)  d_in[0];
    const float* enc   = (const float*)d_in[1];
    const float* act   = (const float*)d_in[2];
    const float* E     = (const float*)d_in[3];
    const float* Ww2h  = (const float*)d_in[4];
    const float* bw2h  = (const float*)d_in[5];
    const float* Wh2h  = (const float*)d_in[6];
    const float* bh2h  = (const float*)d_in[7];
    const float* Ww2hr = (const float*)d_in[8];
    const float* bw2hr = (const float*)d_in[9];
    const float* Wh2hr = (const float*)d_in[10];
    const float* bh2hr = (const float*)d_in[11];
    const float* Wdc   = (const float*)d_in[12];
    const float* Wout  = (const float*)d_in[13];
    const float* bout  = (const float*)d_in[14];
    float* out = (float*)d_out;

    float *pw4, *pwr;
    cudaGetSymbolAddress((void**)&pw4, g_w4);
    cudaGetSymbolAddress((void**)&pwr, g_wr);

    // 1: state init (h = enc, semaphores = 0)
    init_kernel<<<(BATCH*DD + 255) / 256, 256>>>(enc);

    // 2,3: one-time weight transposes
    transpose_w<<<dim3(71, 16), dim3(32, 8)>>>(Wh2h, Wh2hr);
    transpose_wdc<<<dim3(16, 7), dim3(32, 8)>>>(Wdc);

    // 4: W_out permute (must precede fused kernel — GEMM path reads it)
    wout_permute<<<(VV/8)*32*32 / 256, 256>>>(Wout);

    // 5,6: precompute w4_all and wr_all
    {
        dim3 g1((G4 + TS - 1) / TS, (BATCH*TT + TS - 1) / TS);
        gemm_tn<true><<<g1, 256>>>(BATCH*TT, G4, DW, E, tgt, Ww2h, bw2h, pw4, G4);
        dim3 g2((AA + TS - 1) / TS, (BATCH*TT + TS - 1) / TS);
        gemm_tn<true><<<g2, 256>>>(BATCH*TT, AA, DW, E, tgt, Ww2hr, bw2hr, pwr, AA);
    }

    // 7: FUSED recurrence + overlapped output GEMM
    fused_kernel<<<NBLK + NGEMM, NTHR, 48*1024>>>(bh2h, bh2hr, enc, act,
                                                  bout, out);
}

// round 13
// speedup vs baseline: 1.0221x; 1.0221x over previous
#include <cuda_runtime.h>
#include <math.h>

// Problem constants
#define BATCH 32
#define TT 55
#define VV 32000
#define DW 256
#define DD 512
#define AA 200
#define G4 2048   // 4*D
#define NCOL (G4 + AA)   // 2248
#define WTS 2304         // padded row stride of transposed weights

#define NBLK 142           // recurrence blocks
#define NTHR 256
#define NGW  148            // persistent GEMM worker blocks
#define NGRP_M 14           // GEMM m-groups (128 rows each, covers 1792)
#define NGRP_N 250          // GEMM n-groups (128 cols each)
#define NTILES (NGRP_M*NGRP_N)   // 3500

#define MTILES 112          // m16-tile count (t-major: mt = t*2 + (b>=16))

// Scratch (device globals; no allocation allowed)
__device__ float    g_w4[BATCH*TT*G4];
__device__ float    g_wr[BATCH*TT*AA];
__device__ float    g_h[BATCH*DD];
__device__ float    g_dt[BATCH*AA];
__device__ float    g_gates[BATCH*G4];
__device__ uint4    g_wout_p[(VV/8)*32*32];   // W_out tf32, fragment-permuted
__device__ uint4    g_hall_p[MTILES*64*32];   // h_all tf32, fragment-permuted (t-major)
__device__ float    g_wt[DD*WTS];             // [Wh2h ; Wh2hr] transposed [k][col]
__device__ float    g_wdt[AA*DD];             // Wdc transposed [a][j]
__device__ unsigned g_arrA;
__device__ unsigned g_arrB;
__device__ unsigned g_ticket;                 // GEMM tile ticket

// ---------------------------------------------------------------------------
__device__ __forceinline__ unsigned tf32r(float x) {
    unsigned y;
    asm("cvt.rna.tf32.f32 %0, %1;" : "=r"(y) : "f"(x));
    return y;
}

__global__ void init_kernel(const float* __restrict__ enc) {
    int i = blockIdx.x * blockDim.x + threadIdx.x;
    if (i < BATCH*DD) g_h[i] = enc[i];
    if (i == 0) { g_arrA = 0u; g_arrB = 0u; g_ticket = 0u; }
}

__global__ void __launch_bounds__(256) wout_permute(const float* __restrict__ W) {
    int idx = blockIdx.x * blockDim.x + threadIdx.x;
    int lane = idx & 31;
    int sp   = (idx >> 5) & 31;
    int nt   = idx >> 10;
    int g8 = lane >> 2, tq = lane & 3;
    const float* row = W + (size_t)(nt*8 + g8) * DD + sp*16 + tq;
    uint4 o;
    o.x = tf32r(row[0]);
    o.y = tf32r(row[4]);
    o.z = tf32r(row[8]);
    o.w = tf32r(row[12]);
    g_wout_p[idx] = o;
}

// ---- one-time weight transposes -------------------------------------------
__global__ void __launch_bounds__(256) transpose_w(
    const float* __restrict__ Wh2h, const float* __restrict__ Wh2hr)
{
    __shared__ float tile[32][33];
    const int ct = blockIdx.x;
    const int kt = blockIdx.y;
    const int tx = threadIdx.x, ty = threadIdx.y;
    #pragma unroll
    for (int i = 0; i < 4; i++) {
        int col = ct*32 + ty + i*8;
        int k   = kt*32 + tx;
        float v = 0.f;
        if (col < G4)        v = Wh2h[(size_t)col*DD + k];
        else if (col < NCOL) v = Wh2hr[(size_t)(col-G4)*DD + k];
        tile[ty + i*8][tx] = v;
    }
    __syncthreads();
    #pragma unroll
    for (int i = 0; i < 4; i++) {
        int k   = kt*32 + ty + i*8;
        int col = ct*32 + tx;
        g_wt[(size_t)k*WTS + col] = tile[tx][ty + i*8];
    }
}

__global__ void __launch_bounds__(256) transpose_wdc(const float* __restrict__ Wdc)
{
    __shared__ float tile[32][33];
    const int jt = blockIdx.x;
    const int at = blockIdx.y;
    const int tx = threadIdx.x, ty = threadIdx.y;
    #pragma unroll
    for (int i = 0; i < 4; i++) {
        int j = jt*32 + ty + i*8;
        int a = at*32 + tx;
        tile[ty + i*8][tx] = (a < AA) ? Wdc[(size_t)j*AA + a] : 0.f;
    }
    __syncthreads();
    #pragma unroll
    for (int i = 0; i < 4; i++) {
        int a = at*32 + ty + i*8;
        int j = jt*32 + tx;
        if (a < AA) g_wdt[(size_t)a*DD + j] = tile[tx][ty + i*8];
    }
}

__device__ __forceinline__ float sigmoidf_(float x) {
    return 1.f / (1.f + expf(-x));
}

// Fence-free semaphores
__device__ __forceinline__ void sem_arrive(unsigned* ctr) {
    __syncthreads();
    if (threadIdx.x == 0)
        asm volatile("red.release.gpu.global.add.u32 [%0], 1;"
                     :: "l"(ctr) : "memory");
}
__device__ __forceinline__ void sem_wait(unsigned* ctr, unsigned tgt) {
    if (threadIdx.x == 0) {
        unsigned v;
        do {
            asm volatile("ld.acquire.gpu.global.u32 %0, [%1];"
                         : "=r"(v) : "l"(ctr) : "memory");
        } while (v < tgt);
    }
    __syncthreads();
}
// backoff variant (GEMM workers): keeps L2 polling pressure off the semaphore
__device__ __forceinline__ void sem_wait_slow(unsigned* ctr, unsigned tgt) {
    if (threadIdx.x == 0) {
        unsigned v;
        for (;;) {
            asm volatile("ld.acquire.gpu.global.u32 %0, [%1];"
                         : "=r"(v) : "l"(ctr) : "memory");
            if (v >= tgt) break;
            __nanosleep(300);
        }
    }
    __syncthreads();
}

__device__ __forceinline__ void mma_tf32(float c[4],
    unsigned a0, unsigned a1, unsigned a2, unsigned a3,
    unsigned b0, unsigned b1)
{
    asm volatile(
        "mma.sync.aligned.m16n8k8.row.col.f32.tf32.tf32.f32 "
        "{%0,%1,%2,%3}, {%4,%5,%6,%7}, {%8,%9}, {%0,%1,%2,%3};\n"
        : "+f"(c[0]), "+f"(c[1]), "+f"(c[2]), "+f"(c[3])
        : "r"(a0), "r"(a1), "r"(a2), "r"(a3), "r"(b0), "r"(b1));
}

// ---------------------------------------------------------------------------
// FUSED persistent kernel:
//   blocks [0,142): recurrence (reg-resident weights; w4/wr prefetched;
//                   phase2 stores h directly in mma-fragment order, t-major).
//   blocks [142,290): PERSISTENT GEMM workers: ticket-dispensed 128x128
//                   tiles, gated per-tile on g_arrB; fragment-direct.
// Recurrence never waits on GEMM -> deadlock-free; if co-residency fails,
// GEMM drains after the recurrence (graceful).
// ---------------------------------------------------------------------------
__global__ void __launch_bounds__(NTHR, 2) fused_kernel(
    const float* __restrict__ bh2h, const float* __restrict__ bh2hr,
    const float* __restrict__ enc,  const float* __restrict__ act,
    const float* __restrict__ bout, float* __restrict__ out)
{
    extern __shared__ float smem[];

    const int blk  = blockIdx.x;
    const int tid  = threadIdx.x;
    const int w    = tid >> 5;
    const int lane = tid & 31;

    unsigned* arrA; unsigned* arrB;
    asm("cvta.global.u64 %0, g_arrA;" : "=l"(arrA));
    asm("cvta.global.u64 %0, g_arrB;" : "=l"(arrB));

    if (blk < NBLK) {
        // ===================== RECURRENCE PATH =====================
        float* hbuf = smem;           // 8192 floats
        float* part = smem + 8192;    // 4096 floats

        const int colg  = blk >> 1;
        const int bh    = blk & 1;
        const int col   = colg * 32 + lane;
        const int kbase = w * 64;

        // register-resident weights (once)
        float wreg[64];
        #pragma unroll
        for (int i = 0; i < 64; i++)
            wreg[i] = g_wt[(size_t)(kbase + i) * WTS + col];

        // reduction ownership: p0=tid, p1=tid+256
        float biasv[2];
        float dreg[2];
        #pragma unroll
        for (int pi = 0; pi < 2; pi++) {
            int p  = tid + pi * 256;
            int b  = p >> 5;
            int cg = colg * 32 + (p & 31);
            int batch = bh * 16 + b;
            biasv[pi] = 0.f; dreg[pi] = 0.f;
            if (cg < G4) biasv[pi] = bh2h[cg];
            else if (cg < NCOL) {
                biasv[pi] = bh2hr[cg - G4];
                dreg[pi]  = __ldcg(act + batch * AA + (cg - G4));
            }
        }

        // phase2 setup (blocks 0..63)
        const bool p2 = (blk < 64);
        const int  colg2 = blk >> 2;
        const int  b2    = (blk & 3) * 8 + w;
        const int  j2    = colg2 * 32 + lane;
        float creg = 0.f;
        if (p2) creg = __ldcg(enc + b2 * DD + j2);

        // fragment-store index pieces for phase2 h write
        unsigned* hp = (unsigned*)g_hall_p;
        const int fs_lane = (b2 & 7) * 4 + (j2 & 3);
        const int fs_comp = ((b2 >> 3) & 1) + 2 * ((j2 >> 2) & 1);
        const int fs_s    = j2 >> 3;
        const int fs_mth  = (b2 >> 4);

        for (int t = 0; t < TT; t++) {
            sem_wait(arrB, 64u * (unsigned)t);

            // prefetch w4/wr for this step (t-known, independent of phase1)
            float w4v[2];
            #pragma unroll
            for (int pi = 0; pi < 2; pi++) {
                int p  = tid + pi * 256;
                int b  = p >> 5;
                int cg = colg * 32 + (p & 31);
                int batch = bh * 16 + b;
                if (cg < G4)
                    w4v[pi] = __ldcg(&g_w4[(size_t)(batch*TT + t) * G4 + cg]);
                else if (cg < NCOL)
                    w4v[pi] = __ldcg(&g_wr[(size_t)(batch*TT + t) * AA + (cg - G4)]);
                else
                    w4v[pi] = 0.f;
            }

            // stage h rows [bh*16 .. +16) linearly
            {
                const float4* src = (const float4*)(g_h + bh * 16 * DD);
                float4* dst = (float4*)hbuf;
                #pragma unroll
                for (int i = 0; i < 8; i++)
                    dst[i * NTHR + tid] = __ldcg(src + i * NTHR + tid);
            }
            __syncthreads();

            // phase1: two b-halves of 8
            #pragma unroll
            for (int half = 0; half < 2; half++) {
                float acc[8];
                #pragma unroll
                for (int b = 0; b < 8; b++) acc[b] = 0.f;
                const float* hw = hbuf + kbase + half * 8 * DD;
                #pragma unroll
                for (int k4 = 0; k4 < 64; k4 += 4) {
                    float w0 = wreg[k4], w1 = wreg[k4+1];
                    float w2 = wreg[k4+2], w3 = wreg[k4+3];
                    #pragma unroll
                    for (int b = 0; b < 8; b++) {
                        float4 hv = *(const float4*)(hw + b * DD + k4);
                        acc[b] += w0*hv.x + w1*hv.y + w2*hv.z + w3*hv.w;
                    }
                }
                #pragma unroll
                for (int b = 0; b < 8; b++)
                    part[w * 512 + (half * 8 + b) * 32 + lane] = acc[b];
            }
            __syncthreads();

            // reduce partials, activate, store gates / update dt
            #pragma unroll
            for (int pi = 0; pi < 2; pi++) {
                int p  = tid + pi * 256;
                float s = part[p]          + part[p + 512]
                        + part[p + 1024]   + part[p + 1536]
                        + part[p + 2048]   + part[p + 2560]
                        + part[p + 3072]   + part[p + 3584];
                int b  = p >> 5;
                int cg = colg * 32 + (p & 31);
                int batch = bh * 16 + b;
                if (cg < G4) {
                    float v = w4v[pi] + s + biasv[pi];
                    v = (cg < 3*DD) ? sigmoidf_(v) : tanhf(v);
                    g_gates[batch * G4 + cg] = v;
                } else if (cg < NCOL) {
                    float r = sigmoidf_(w4v[pi] + s + biasv[pi]);
                    dreg[pi] *= r;
                    g_dt[batch * AA + (cg - G4)] = dreg[pi];
                }
            }

            sem_arrive(arrA);

            if (p2) {
                sem_wait(arrA, 142u * (unsigned)(t + 1));

                int bb = (blk & 3) * 8;
                for (int i = tid; i < 8 * AA; i += NTHR)
                    part[i] = __ldcg(g_dt + bb * AA + i);
                __syncthreads();

                const float* wdt = g_wdt + j2;
                const float* dts = part + w * AA;
                float acc_a = 0.f, acc_b = 0.f;
                #pragma unroll 10
                for (int a = 0; a < AA; a += 2) {
                    acc_a += dts[a    ] * wdt[(a    ) * DD];
                    acc_b += dts[a + 1] * wdt[(a + 1) * DD];
                }
                float dtw = tanhf(acc_a + acc_b);
                float gi = __ldcg(g_gates + b2 * G4 + j2);
                float gf = __ldcg(g_gates + b2 * G4 + DD   + j2);
                float go = __ldcg(g_gates + b2 * G4 + 2*DD + j2);
                float ch = __ldcg(g_gates + b2 * G4 + 3*DD + j2);
                creg = gf * creg + gi * ch + dtw;
                float h = go * tanhf(creg);
                g_h[b2 * DD + j2] = h;
                int mt = t * 2 + fs_mth;
                hp[(((size_t)mt * 64 + fs_s) * 32 + fs_lane) * 4 + fs_comp] = tf32r(h);

                sem_arrive(arrB);
            }
        }
    } else {
        // ============ PERSISTENT GEMM WORKER PATH ============
        unsigned* tk_sh = (unsigned*)smem;

        const int wmh = (w & 1);             // m half (0/1), 64 rows
        const int wnq = (w >> 1);            // n quarter, 32 cols
        const int g8  = lane >> 2;
        const int tq  = lane & 3;

        for (;;) {
            if (tid == 0) tk_sh[0] = atomicAdd(&g_ticket, 1u);
            __syncthreads();
            unsigned tau = tk_sh[0];
            __syncthreads();
            if (tau >= NTILES) break;

            const int mg = tau / NGRP_N;     // 128 rows = t in [4mg, 4mg+4)
            const int ng = tau % NGRP_N;     // 128 cols

            int t_need = 4*mg + 3; if (t_need > TT-1) t_need = TT-1;
            sem_wait_slow(arrB, 64u * (unsigned)(t_need + 1));

            const uint4* aBase = g_hall_p + ((size_t)(mg*8 + wmh*4) * 64) * 32 + lane;
            const uint4* bBase = g_wout_p + ((size_t)(ng*16 + wnq*4) * 32) * 32 + lane;

            float acc[4][4][4];
            #pragma unroll
            for (int mi = 0; mi < 4; mi++)
                #pragma unroll
                for (int ni = 0; ni < 4; ni++)
                    #pragma unroll
                    for (int q = 0; q < 4; q++) acc[mi][ni][q] = 0.f;

            #pragma unroll 1
            for (int kt = 0; kt < 16; kt++) {
                #pragma unroll
                for (int sp = 0; sp < 2; sp++) {
                    uint4 bf[4];
                    #pragma unroll
                    for (int ni = 0; ni < 4; ni++)
                        bf[ni] = __ldg(bBase + ((size_t)ni * 32 + kt*2 + sp) * 32);
                    #pragma unroll
                    for (int h = 0; h < 2; h++) {
                        const int s = kt*4 + sp*2 + h;
                        uint4 af[4];
                        #pragma unroll
                        for (int mi = 0; mi < 4; mi++)
                            af[mi] = __ldcg(aBase + ((size_t)mi * 64 + s) * 32);
                        #pragma unroll
                        for (int mi = 0; mi < 4; mi++)
                            #pragma unroll
                            for (int ni = 0; ni < 4; ni++) {
                                unsigned b0 = h ? bf[ni].z : bf[ni].x;
                                unsigned b1 = h ? bf[ni].w : bf[ni].y;
                                mma_tf32(acc[mi][ni], af[mi].x, af[mi].y,
                                         af[mi].z, af[mi].w, b0, b1);
                            }
                    }
                }
            }

            // epilogue: gm -> t = gm>>5, b = gm&31; out[(b*TT+t)*VV + gn]
            #pragma unroll
            for (int mi = 0; mi < 4; mi++) {
                int gm0 = mg*128 + wmh*64 + mi*16 + g8;
                #pragma unroll
                for (int half = 0; half < 2; half++) {
                    int gm = gm0 + half*8;
                    int t  = gm >> 5;
                    if (t < TT) {
                        int b = gm & 31;
                        float* orow = out + ((size_t)b * TT + t) * VV;
                        #pragma unroll
                        for (int ni = 0; ni < 4; ni++) {
                            int gn = ng*128 + wnq*32 + ni*8 + tq*2;
                            float2 bs = *(const float2*)(bout + gn);
                            float2 o;
                            o.x = acc[mi][ni][half*2    ] + bs.x;
                            o.y = acc[mi][ni][half*2 + 1] + bs.y;
                            *(float2*)(orow + gn) = o;
                        }
                    }
                }
            }
            __syncthreads();
        }
    }
}

// ---------------------------------------------------------------------------
// fp32 tiled GEMM (two small precompute GEMMs)
// ---------------------------------------------------------------------------
#define TS 128
#define KT 8

template<bool GATHER>
__global__ void __launch_bounds__(256) gemm_tn(
    int M, int N, int K,
    const float* __restrict__ A, const int* __restrict__ idx,
    const float* __restrict__ B,
    const float* __restrict__ bias,
    float* __restrict__ C, int ldc)
{
    __shared__ float As[KT][TS];
    __shared__ float Bs[KT][TS];

    int tid = threadIdx.x;
    int lrow = tid >> 1;
    int kc   = (tid & 1) * 4;

    int gm_l = blockIdx.y * TS + lrow;
    int gn_l = blockIdx.x * TS + lrow;

    const float* aptr = nullptr;
    if (gm_l < M) {
        int ar = GATHER ? idx[gm_l] : gm_l;
        aptr = A + (size_t)ar * K;
    }
    const float* bptr = (gn_l < N) ? (B + (size_t)gn_l * K) : nullptr;

    int tx = tid & 15;
    int ty = tid >> 4;

    float acc[8][8];
    #pragma unroll
    for (int i = 0; i < 8; i++)
        #pragma unroll
        for (int j = 0; j < 8; j++) acc[i][j] = 0.f;

    for (int k0 = 0; k0 < K; k0 += KT) {
        float4 av = make_float4(0.f, 0.f, 0.f, 0.f);
        float4 bv = make_float4(0.f, 0.f, 0.f, 0.f);
        if (aptr) av = *(const float4*)(aptr + k0 + kc);
        if (bptr) bv = *(const float4*)(bptr + k0 + kc);
        __syncthreads();
        As[kc+0][lrow] = av.x; As[kc+1][lrow] = av.y;
        As[kc+2][lrow] = av.z; As[kc+3][lrow] = av.w;
        Bs[kc+0][lrow] = bv.x; Bs[kc+1][lrow] = bv.y;
        Bs[kc+2][lrow] = bv.z; Bs[kc+3][lrow] = bv.w;
        __syncthreads();
        #pragma unroll
        for (int kk = 0; kk < KT; kk++) {
            float4 a0 = *(const float4*)&As[kk][ty*8];
            float4 a1 = *(const float4*)&As[kk][ty*8+4];
            float4 b0 = *(const float4*)&Bs[kk][tx*8];
            float4 b1 = *(const float4*)&Bs[kk][tx*8+4];
            float a[8] = {a0.x,a0.y,a0.z,a0.w,a1.x,a1.y,a1.z,a1.w};
            float b[8] = {b0.x,b0.y,b0.z,b0.w,b1.x,b1.y,b1.z,b1.w};
            #pragma unroll
            for (int i = 0; i < 8; i++)
                #pragma unroll
                for (int j = 0; j < 8; j++)
                    acc[i][j] += a[i] * b[j];
        }
    }

    #pragma unroll
    for (int i = 0; i < 8; i++) {
        int gm = blockIdx.y * TS + ty*8 + i;
        if (gm < M) {
            #pragma unroll
            for (int j = 0; j < 8; j += 4) {
                int gn = blockIdx.x * TS + tx*8 + j;
                if (gn < N) {
                    float4 bs = *(const float4*)(bias + gn);
                    float4 o;
                    o.x = acc[i][j+0] + bs.x;
                    o.y = acc[i][j+1] + bs.y;
                    o.z = acc[i][j+2] + bs.z;
                    o.w = acc[i][j+3] + bs.w;
                    *(float4*)(C + (size_t)gm * ldc + gn) = o;
                }
            }
        }
    }
}

// ---------------------------------------------------------------------------
// Launch
// ---------------------------------------------------------------------------
extern "C" void kernel_launch(void* const* d_in, const int* in_sizes, int n_in,
                              void* d_out, int out_size) {
    const int*   tgt   = (const int*)  d_in[0];
    const float* enc   = (const float*)d_in[1];
    const float* act   = (const float*)d_in[2];
    const float* E     = (const float*)d_in[3];
    const float* Ww2h  = (const float*)d_in[4];
    const float* bw2h  = (const float*)d_in[5];
    const float* Wh2h  = (const float*)d_in[6];
    const float* bh2h  = (const float*)d_in[7];
    const float* Ww2hr = (const float*)d_in[8];
    const float* bw2hr = (const float*)d_in[9];
    const float* Wh2hr = (const float*)d_in[10];
    const float* bh2hr = (const float*)d_in[11];
    const float* Wdc   = (const float*)d_in[12];
    const float* Wout  = (const float*)d_in[13];
    const float* bout  = (const float*)d_in[14];
    float* out = (float*)d_out;

    float *pw4, *pwr;
    cudaGetSymbolAddress((void**)&pw4, g_w4);
    cudaGetSymbolAddress((void**)&pwr, g_wr);

    // 1: state init
    init_kernel<<<(BATCH*DD + 255) / 256, 256>>>(enc);

    // 2,3: one-time weight transposes
    transpose_w<<<dim3(71, 16), dim3(32, 8)>>>(Wh2h, Wh2hr);
    transpose_wdc<<<dim3(16, 7), dim3(32, 8)>>>(Wdc);

    // 4: W_out permute (GEMM path reads it)
    wout_permute<<<(VV/8)*32*32 / 256, 256>>>(Wout);

    // 5,6: precompute w4_all and wr_all
    {
        dim3 g1((G4 + TS - 1) / TS, (BATCH*TT + TS - 1) / TS);
        gemm_tn<true><<<g1, 256>>>(BATCH*TT, G4, DW, E, tgt, Ww2h, bw2h, pw4, G4);
        dim3 g2((AA + TS - 1) / TS, (BATCH*TT + TS - 1) / TS);
        gemm_tn<true><<<g2, 256>>>(BATCH*TT, AA, DW, E, tgt, Ww2hr, bw2hr, pwr, AA);
    }

    // 7: FUSED recurrence + persistent overlapped output GEMM
    fused_kernel<<<NBLK + NGW, NTHR, 48*1024>>>(bh2h, bh2hr, enc, act,
                                                bout, out);
}

// round 15
// speedup vs baseline: 1.1719x; 1.1466x over previous
#include <cuda_runtime.h>
#include <cuda_fp16.h>
#include <math.h>

// Problem constants
#define BATCH 32
#define TT 55
#define VV 32000
#define DW 256
#define DD 512
#define AA 200
#define G4 2048   // 4*D
#define NCOL (G4 + AA)   // 2248
#define WTS 2304         // padded row stride of transposed weights

#define NBLK 142   // recurrence blocks
#define NTHR 256

#define MTILES 112       // padded m16-tile count (ceil(1760/16)=110 -> 112)

// Scratch (device globals; no allocation allowed)
__device__ float    g_w4[BATCH*TT*G4];
__device__ float    g_wr[BATCH*TT*AA];
__device__ float    g_h[BATCH*DD];
__device__ float    g_dt[BATCH*AA];
__device__ float    g_gates[BATCH*G4];
__device__ __half   g_hall_h[BATCH*TT*DD];    // h_all fp16, linear [m][k]
__device__ uint2    g_wout_p2[(VV/8)*32*32];  // W_out fp16 fragment-packed (32MB)
__device__ uint4    g_hall_p4[MTILES*32*32];  // h_all fp16 fragment-packed
__device__ float    g_wt[DD*WTS];             // [Wh2h;Wh2hr] transposed [k][col]
__device__ float    g_wdt[AA*DD];             // Wdc transposed [a][j]
__device__ unsigned g_arrA;
__device__ unsigned g_arrB;

// ---------------------------------------------------------------------------
__global__ void init_kernel(const float* __restrict__ enc) {
    int i = blockIdx.x * blockDim.x + threadIdx.x;
    if (i < BATCH*DD) g_h[i] = enc[i];
    if (i == 0) { g_arrA = 0u; g_arrB = 0u; }
}

__device__ __forceinline__ unsigned pack_h2(float a, float b) {
    unsigned lo = __half_as_ushort(__float2half_rn(a));
    unsigned hi = __half_as_ushort(__float2half_rn(b));
    return lo | (hi << 16);
}

// W_out -> fp16 fragment-packed B operand (m16n8k16 layout).
// B frag (16x8, col): b0 = (k=2tq..+1, n=g8), b1 = (k=2tq+8..+9, n=g8).
// Index (nt, s, lane): uint2{b0,b1} at (nt*32 + s)*32 + lane.
__global__ void __launch_bounds__(256) wout_permute_h(const float* __restrict__ W) {
    int idx = blockIdx.x * blockDim.x + threadIdx.x;
    int lane = idx & 31;
    int s    = (idx >> 5) & 31;
    int nt   = idx >> 10;            // 0..3999
    int g8 = lane >> 2, tq = lane & 3;
    const float* row = W + (size_t)(nt*8 + g8) * DD + s*16;
    float2 p0 = *(const float2*)(row + 2*tq);
    float2 p1 = *(const float2*)(row + 2*tq + 8);
    g_wout_p2[idx] = make_uint2(pack_h2(p0.x, p0.y), pack_h2(p1.x, p1.y));
}

// h_all fp16 linear -> fragment-packed A operand (m16n8k16 layout).
// A frag (16x16 row): a0=(g8, 2tq..+1) a1=(g8+8, ..) a2=(g8, 2tq+8..+9) a3=(g8+8, ..).
__global__ void __launch_bounds__(256) a_permute_h() {
    int idx = blockIdx.x * blockDim.x + threadIdx.x;
    if (idx >= MTILES*32*32) return;
    int lane = idx & 31;
    int s    = (idx >> 5) & 31;
    int mt   = idx >> 10;            // 0..111
    int g8 = lane >> 2, tq = lane & 3;
    int m0 = mt*16 + g8, m1 = m0 + 8;
    int k0 = s*16 + 2*tq;
    unsigned a0 = 0u, a1 = 0u, a2 = 0u, a3 = 0u;
    if (m0 < BATCH*TT) {
        a0 = *(const unsigned*)(g_hall_h + (size_t)m0*DD + k0);
        a2 = *(const unsigned*)(g_hall_h + (size_t)m0*DD + k0 + 8);
    }
    if (m1 < BATCH*TT) {
        a1 = *(const unsigned*)(g_hall_h + (size_t)m1*DD + k0);
        a3 = *(const unsigned*)(g_hall_h + (size_t)m1*DD + k0 + 8);
    }
    g_hall_p4[idx] = make_uint4(a0, a1, a2, a3);
}

// ---- one-time weight transposes -------------------------------------------
__global__ void __launch_bounds__(256) transpose_w(
    const float* __restrict__ Wh2h, const float* __restrict__ Wh2hr)
{
    __shared__ float tile[32][33];
    const int ct = blockIdx.x;
    const int kt = blockIdx.y;
    const int tx = threadIdx.x, ty = threadIdx.y;
    #pragma unroll
    for (int i = 0; i < 4; i++) {
        int col = ct*32 + ty + i*8;
        int k   = kt*32 + tx;
        float v = 0.f;
        if (col < G4)        v = Wh2h[(size_t)col*DD + k];
        else if (col < NCOL) v = Wh2hr[(size_t)(col-G4)*DD + k];
        tile[ty + i*8][tx] = v;
    }
    __syncthreads();
    #pragma unroll
    for (int i = 0; i < 4; i++) {
        int k   = kt*32 + ty + i*8;
        int col = ct*32 + tx;
        g_wt[(size_t)k*WTS + col] = tile[tx][ty + i*8];
    }
}

__global__ void __launch_bounds__(256) transpose_wdc(const float* __restrict__ Wdc)
{
    __shared__ float tile[32][33];
    const int jt = blockIdx.x;
    const int at = blockIdx.y;
    const int tx = threadIdx.x, ty = threadIdx.y;
    #pragma unroll
    for (int i = 0; i < 4; i++) {
        int j = jt*32 + ty + i*8;
        int a = at*32 + tx;
        tile[ty + i*8][tx] = (a < AA) ? Wdc[(size_t)j*AA + a] : 0.f;
    }
    __syncthreads();
    #pragma unroll
    for (int i = 0; i < 4; i++) {
        int a = at*32 + ty + i*8;
        int j = jt*32 + tx;
        if (a < AA) g_wdt[(size_t)a*DD + j] = tile[tx][ty + i*8];
    }
}

__device__ __forceinline__ float sigmoidf_(float x) {
    return 1.f / (1.f + expf(-x));
}

// Fence-free semaphores
__device__ __forceinline__ void sem_arrive(unsigned* ctr) {
    __syncthreads();
    if (threadIdx.x == 0)
        asm volatile("red.release.gpu.global.add.u32 [%0], 1;"
                     :: "l"(ctr) : "memory");
}
__device__ __forceinline__ void sem_wait(unsigned* ctr, unsigned tgt) {
    if (threadIdx.x == 0) {
        unsigned v;
        do {
            asm volatile("ld.acquire.gpu.global.u32 %0, [%1];"
                         : "=r"(v) : "l"(ctr) : "memory");
        } while (v < tgt);
    }
    __syncthreads();
}

// ---------------------------------------------------------------------------
// Persistent recurrence kernel — R11 structure verbatim (measured best);
// only change: h_all stored as fp16.
// ---------------------------------------------------------------------------
__global__ void __launch_bounds__(NTHR, 1) recurrent_kernel(
    const float* __restrict__ bh2h, const float* __restrict__ bh2hr,
    const float* __restrict__ enc,  const float* __restrict__ act)
{
    extern __shared__ float smem[];
    float* hbuf = smem;           // 8192 floats
    float* part = smem + 8192;    // 4096 floats

    const int blk  = blockIdx.x;
    const int tid  = threadIdx.x;
    const int w    = tid >> 5;
    const int lane = tid & 31;

    const int colg  = blk >> 1;
    const int bh    = blk & 1;
    const int col   = colg * 32 + lane;
    const int kbase = w * 64;

    float wreg[64];
    #pragma unroll
    for (int i = 0; i < 64; i++)
        wreg[i] = g_wt[(size_t)(kbase + i) * WTS + col];

    float biasv[2];
    float dreg[2];
    #pragma unroll
    for (int pi = 0; pi < 2; pi++) {
        int p  = tid + pi * 256;
        int b  = p >> 5;
        int cg = colg * 32 + (p & 31);
        int batch = bh * 16 + b;
        biasv[pi] = 0.f; dreg[pi] = 0.f;
        if (cg < G4) biasv[pi] = bh2h[cg];
        else if (cg < NCOL) {
            biasv[pi] = bh2hr[cg - G4];
            dreg[pi]  = __ldcg(act + batch * AA + (cg - G4));
        }
    }

    const bool p2 = (blk < 64);
    const int  colg2 = blk >> 2;
    const int  b2    = (blk & 3) * 8 + w;
    const int  j2    = colg2 * 32 + lane;
    float creg = 0.f;
    if (p2) creg = __ldcg(enc + b2 * DD + j2);

    unsigned* arrA; unsigned* arrB;
    asm("cvta.global.u64 %0, g_arrA;" : "=l"(arrA));
    asm("cvta.global.u64 %0, g_arrB;" : "=l"(arrB));

    for (int t = 0; t < TT; t++) {
        sem_wait(arrB, 64u * (unsigned)t);

        {
            const float4* src = (const float4*)(g_h + bh * 16 * DD);
            float4* dst = (float4*)hbuf;
            #pragma unroll
            for (int i = 0; i < 8; i++)
                dst[i * NTHR + tid] = __ldcg(src + i * NTHR + tid);
        }
        __syncthreads();

        {
            float acc[16];
            #pragma unroll
            for (int b = 0; b < 16; b++) acc[b] = 0.f;
            const float* hw = hbuf + kbase;
            #pragma unroll
            for (int k4 = 0; k4 < 64; k4 += 4) {
                float w0 = wreg[k4], w1 = wreg[k4+1];
                float w2 = wreg[k4+2], w3 = wreg[k4+3];
                #pragma unroll
                for (int b = 0; b < 16; b++) {
                    float4 hv = *(const float4*)(hw + b * DD + k4);
                    acc[b] += w0*hv.x + w1*hv.y + w2*hv.z + w3*hv.w;
                }
            }
            #pragma unroll
            for (int b = 0; b < 16; b++)
                part[w * 512 + b * 32 + lane] = acc[b];
        }
        __syncthreads();

        #pragma unroll
        for (int pi = 0; pi < 2; pi++) {
            int p  = tid + pi * 256;
            float s = part[p]          + part[p + 512]
                    + part[p + 1024]   + part[p + 1536]
                    + part[p + 2048]   + part[p + 2560]
                    + part[p + 3072]   + part[p + 3584];
            int b  = p >> 5;
            int cg = colg * 32 + (p & 31);
            int batch = bh * 16 + b;
            if (cg < G4) {
                float v = g_w4[(size_t)(batch*TT + t) * G4 + cg] + s + biasv[pi];
                v = (cg < 3*DD) ? sigmoidf_(v) : tanhf(v);
                g_gates[batch * G4 + cg] = v;
            } else if (cg < NCOL) {
                int acol = cg - G4;
                float r = sigmoidf_(g_wr[(size_t)(batch*TT + t) * AA + acol]
                                    + s + biasv[pi]);
                dreg[pi] *= r;
                g_dt[batch * AA + acol] = dreg[pi];
            }
        }

        sem_arrive(arrA);

        if (p2) {
            sem_wait(arrA, 142u * (unsigned)(t + 1));

            int bb = (blk & 3) * 8;
            for (int i = tid; i < 8 * AA; i += NTHR)
                part[i] = __ldcg(g_dt + bb * AA + i);
            __syncthreads();

            const float* wdt = g_wdt + j2;
            const float* dts = part + w * AA;
            float acc_a = 0.f, acc_b = 0.f;
            #pragma unroll 10
            for (int a = 0; a < AA; a += 2) {
                acc_a += dts[a    ] * wdt[(a    ) * DD];
                acc_b += dts[a + 1] * wdt[(a + 1) * DD];
            }
            float dtw = tanhf(acc_a + acc_b);
            float gi = __ldcg(g_gates + b2 * G4 + j2);
            float gf = __ldcg(g_gates + b2 * G4 + DD   + j2);
            float go = __ldcg(g_gates + b2 * G4 + 2*DD + j2);
            float ch = __ldcg(g_gates + b2 * G4 + 3*DD + j2);
            creg = gf * creg + gi * ch + dtw;
            float h = go * tanhf(creg);
            g_h[b2 * DD + j2] = h;
            g_hall_h[(size_t)(b2 * TT + t) * DD + j2] = __float2half_rn(h);

            sem_arrive(arrB);
        }
    }
}

// ---------------------------------------------------------------------------
// fp32 tiled GEMM (two small precompute GEMMs)
// ---------------------------------------------------------------------------
#define TS 128
#define KT 8

template<bool GATHER>
__global__ void __launch_bounds__(256) gemm_tn(
    int M, int N, int K,
    const float* __restrict__ A, const int* __restrict__ idx,
    const float* __restrict__ B,
    const float* __restrict__ bias,
    float* __restrict__ C, int ldc)
{
    __shared__ float As[KT][TS];
    __shared__ float Bs[KT][TS];

    int tid = threadIdx.x;
    int lrow = tid >> 1;
    int kc   = (tid & 1) * 4;

    int gm_l = blockIdx.y * TS + lrow;
    int gn_l = blockIdx.x * TS + lrow;

    const float* aptr = nullptr;
    if (gm_l < M) {
        int ar = GATHER ? idx[gm_l] : gm_l;
        aptr = A + (size_t)ar * K;
    }
    const float* bptr = (gn_l < N) ? (B + (size_t)gn_l * K) : nullptr;

    int tx = tid & 15;
    int ty = tid >> 4;

    float acc[8][8];
    #pragma unroll
    for (int i = 0; i < 8; i++)
        #pragma unroll
        for (int j = 0; j < 8; j++) acc[i][j] = 0.f;

    for (int k0 = 0; k0 < K; k0 += KT) {
        float4 av = make_float4(0.f, 0.f, 0.f, 0.f);
        float4 bv = make_float4(0.f, 0.f, 0.f, 0.f);
        if (aptr) av = *(const float4*)(aptr + k0 + kc);
        if (bptr) bv = *(const float4*)(bptr + k0 + kc);
        __syncthreads();
        As[kc+0][lrow] = av.x; As[kc+1][lrow] = av.y;
        As[kc+2][lrow] = av.z; As[kc+3][lrow] = av.w;
        Bs[kc+0][lrow] = bv.x; Bs[kc+1][lrow] = bv.y;
        Bs[kc+2][lrow] = bv.z; Bs[kc+3][lrow] = bv.w;
        __syncthreads();
        #pragma unroll
        for (int kk = 0; kk < KT; kk++) {
            float4 a0 = *(const float4*)&As[kk][ty*8];
            float4 a1 = *(const float4*)&As[kk][ty*8+4];
            float4 b0 = *(const float4*)&Bs[kk][tx*8];
            float4 b1 = *(const float4*)&Bs[kk][tx*8+4];
            float a[8] = {a0.x,a0.y,a0.z,a0.w,a1.x,a1.y,a1.z,a1.w};
            float b[8] = {b0.x,b0.y,b0.z,b0.w,b1.x,b1.y,b1.z,b1.w};
            #pragma unroll
            for (int i = 0; i < 8; i++)
                #pragma unroll
                for (int j = 0; j < 8; j++)
                    acc[i][j] += a[i] * b[j];
        }
    }

    #pragma unroll
    for (int i = 0; i < 8; i++) {
        int gm = blockIdx.y * TS + ty*8 + i;
        if (gm < M) {
            #pragma unroll
            for (int j = 0; j < 8; j += 4) {
                int gn = blockIdx.x * TS + tx*8 + j;
                if (gn < N) {
                    float4 bs = *(const float4*)(bias + gn);
                    float4 o;
                    o.x = acc[i][j+0] + bs.x;
                    o.y = acc[i][j+1] + bs.y;
                    o.z = acc[i][j+2] + bs.z;
                    o.w = acc[i][j+3] + bs.w;
                    *(float4*)(C + (size_t)gm * ldc + gn) = o;
                }
            }
        }
    }
}

// ---------------------------------------------------------------------------
// fp16 fragment-direct output GEMM (m16n8k16, fp32 accumulate).
// CTA 128x256 (8 warps, warp tile 64x64: 4 m16-tiles x 8 n8-tiles).
// Operands pre-permuted to exact fragment order; no smem, no barriers.
// ---------------------------------------------------------------------------
__device__ __forceinline__ void mma_fp16(float c[4],
    unsigned a0, unsigned a1, unsigned a2, unsigned a3,
    unsigned b0, unsigned b1)
{
    asm volatile(
        "mma.sync.aligned.m16n8k16.row.col.f32.f16.f16.f32 "
        "{%0,%1,%2,%3}, {%4,%5,%6,%7}, {%8,%9}, {%0,%1,%2,%3};\n"
        : "+f"(c[0]), "+f"(c[1]), "+f"(c[2]), "+f"(c[3])
        : "r"(a0), "r"(a1), "r"(a2), "r"(a3), "r"(b0), "r"(b1));
}

__global__ void __launch_bounds__(256, 1) gemm_fp16(
    int M,
    const float* __restrict__ bias,
    float* __restrict__ C, int ldc)
{
    const int tid  = threadIdx.x;
    const int lane = tid & 31;
    const int w    = tid >> 5;
    const int wmh  = (w & 1);            // m half
    const int wnq  = (w >> 1);           // n quarter
    const int g8   = lane >> 2;
    const int tq   = lane & 3;

    const int bMt = blockIdx.y * 8 + wmh * 4;    // base m16-tile (4 per warp)
    const int bNt = blockIdx.x * 32 + wnq * 8;   // base n8-tile (8 per warp)

    const uint4* aBase = g_hall_p4 + (size_t)bMt * 32 * 32 + lane;
    const uint2* bBase = g_wout_p2 + (size_t)bNt * 32 * 32 + lane;

    float acc[4][8][4];
    #pragma unroll
    for (int mi = 0; mi < 4; mi++)
        #pragma unroll
        for (int ni = 0; ni < 8; ni++)
            #pragma unroll
            for (int q = 0; q < 4; q++) acc[mi][ni][q] = 0.f;

    #pragma unroll 1
    for (int kt = 0; kt < 32; kt++) {     // 32 k16-tiles over K=512
        uint2 bf[8];
        #pragma unroll
        for (int ni = 0; ni < 8; ni++)
            bf[ni] = __ldg(bBase + ((size_t)ni * 32 + kt) * 32);
        uint4 af[4];
        #pragma unroll
        for (int mi = 0; mi < 4; mi++)
            af[mi] = __ldg(aBase + ((size_t)mi * 32 + kt) * 32);
        #pragma unroll
        for (int mi = 0; mi < 4; mi++)
            #pragma unroll
            for (int ni = 0; ni < 8; ni++)
                mma_fp16(acc[mi][ni], af[mi].x, af[mi].y, af[mi].z, af[mi].w,
                         bf[ni].x, bf[ni].y);
    }

    // epilogue: C frag m16n8: (c0,c1) row g8 cols 2tq,2tq+1; (c2,c3) row g8+8
    #pragma unroll
    for (int mi = 0; mi < 4; mi++) {
        int gm0 = blockIdx.y * 128 + wmh * 64 + mi*16 + g8;
        int gm1 = gm0 + 8;
        #pragma unroll
        for (int ni = 0; ni < 8; ni++) {
            int gn = blockIdx.x * 256 + wnq * 64 + ni*8 + tq*2;
            float2 bs = *(const float2*)(bias + gn);
            if (gm0 < M) {
                float2 o0; o0.x = acc[mi][ni][0] + bs.x; o0.y = acc[mi][ni][1] + bs.y;
                *(float2*)(C + (size_t)gm0 * ldc + gn) = o0;
            }
            if (gm1 < M) {
                float2 o1; o1.x = acc[mi][ni][2] + bs.x; o1.y = acc[mi][ni][3] + bs.y;
                *(float2*)(C + (size_t)gm1 * ldc + gn) = o1;
            }
        }
    }
}

// ---------------------------------------------------------------------------
// Launch
// ---------------------------------------------------------------------------
extern "C" void kernel_launch(void* const* d_in, const int* in_sizes, int n_in,
                              void* d_out, int out_size) {
    const int*   tgt   = (const int*)  d_in[0];
    const float* enc   = (const float*)d_in[1];
    const float* act   = (const float*)d_in[2];
    const float* E     = (const float*)d_in[3];
    const float* Ww2h  = (const float*)d_in[4];
    const float* bw2h  = (const float*)d_in[5];
    const float* Wh2h  = (const float*)d_in[6];
    const float* bh2h  = (const float*)d_in[7];
    const float* Ww2hr = (const float*)d_in[8];
    const float* bw2hr = (const float*)d_in[9];
    const float* Wh2hr = (const float*)d_in[10];
    const float* bh2hr = (const float*)d_in[11];
    const float* Wdc   = (const float*)d_in[12];
    const float* Wout  = (const float*)d_in[13];
    const float* bout  = (const float*)d_in[14];
    float* out = (float*)d_out;

    float *pw4, *pwr;
    cudaGetSymbolAddress((void**)&pw4, g_w4);
    cudaGetSymbolAddress((void**)&pwr, g_wr);

    // 1: state init
    init_kernel<<<(BATCH*DD + 255) / 256, 256>>>(enc);

    // 2,3: one-time weight transposes (recurrence inputs)
    transpose_w<<<dim3(71, 16), dim3(32, 8)>>>(Wh2h, Wh2hr);
    transpose_wdc<<<dim3(16, 7), dim3(32, 8)>>>(Wdc);

    // 4: W_out -> fp16 fragment-packed
    wout_permute_h<<<(VV/8)*32*32 / 256, 256>>>(Wout);

    // 5,6: precompute w4_all and wr_all
    {
        dim3 g1((G4 + TS - 1) / TS, (BATCH*TT + TS - 1) / TS);
        gemm_tn<true><<<g1, 256>>>(BATCH*TT, G4, DW, E, tgt, Ww2h, bw2h, pw4, G4);
        dim3 g2((AA + TS - 1) / TS, (BATCH*TT + TS - 1) / TS);
        gemm_tn<true><<<g2, 256>>>(BATCH*TT, AA, DW, E, tgt, Ww2hr, bw2hr, pwr, AA);
    }

    // 7: recurrence (R11 split — measured best)
    recurrent_kernel<<<NBLK, NTHR, 48*1024>>>(bh2h, bh2hr, enc, act);

    // 8: h_all -> fp16 fragment-packed
    a_permute_h<<<(MTILES*32*32 + 255) / 256, 256>>>();

    // 9: fp16 tensor-core output projection
    {
        dim3 g3(VV / 256, (BATCH*TT + 127) / 128);   // 125 x 14
        gemm_fp16<<<g3, 256>>>(BATCH*TT, bout, out, VV);
    }
}

// round 16
// speedup vs baseline: 1.2037x; 1.0272x over previous
#include <cuda_runtime.h>
#include <cuda_fp16.h>
#include <math.h>

// Problem constants
#define BATCH 32
#define TT 55
#define VV 32000
#define DW 256
#define DD 512
#define AA 200
#define G4 2048   // 4*D
#define NCOL (G4 + AA)   // 2248
#define WTS 2304         // padded row stride of transposed weights

#define NBLK 142   // recurrence blocks
#define NTHR 256

#define MTILES 112       // padded m16-tile count (ceil(1760/16)=110 -> 112)

// Scratch (device globals; no allocation allowed)
__device__ float    g_w4[BATCH*TT*G4];
__device__ float    g_wr[BATCH*TT*AA];
__device__ float    g_h[BATCH*DD];
__device__ float    g_dt[BATCH*AA];
__device__ float    g_gates[BATCH*G4];
__device__ __half   g_hall_h[BATCH*TT*DD];    // h_all fp16, linear [m][k]
__device__ uint2    g_wout_p2[(VV/8)*32*32];  // W_out fp16 fragment-packed (32MB)
__device__ uint4    g_hall_p4[MTILES*32*32];  // h_all fp16 fragment-packed
__device__ float    g_wt[DD*WTS];             // [Wh2h;Wh2hr] transposed [k][col]
__device__ float    g_wdt[AA*DD];             // Wdc transposed [a][j]
__device__ unsigned g_arrA;
__device__ unsigned g_arrB;

// ---------------------------------------------------------------------------
__global__ void init_kernel(const float* __restrict__ enc) {
    int i = blockIdx.x * blockDim.x + threadIdx.x;
    if (i < BATCH*DD) g_h[i] = enc[i];
    if (i == 0) { g_arrA = 0u; g_arrB = 0u; }
}

__device__ __forceinline__ unsigned pack_h2(float a, float b) {
    unsigned lo = __half_as_ushort(__float2half_rn(a));
    unsigned hi = __half_as_ushort(__float2half_rn(b));
    return lo | (hi << 16);
}

// W_out -> fp16 fragment-packed B operand (m16n8k16 layout).
__global__ void __launch_bounds__(256) wout_permute_h(const float* __restrict__ W) {
    int idx = blockIdx.x * blockDim.x + threadIdx.x;
    int lane = idx & 31;
    int s    = (idx >> 5) & 31;
    int nt   = idx >> 10;            // 0..3999
    int g8 = lane >> 2, tq = lane & 3;
    const float* row = W + (size_t)(nt*8 + g8) * DD + s*16;
    float2 p0 = *(const float2*)(row + 2*tq);
    float2 p1 = *(const float2*)(row + 2*tq + 8);
    g_wout_p2[idx] = make_uint2(pack_h2(p0.x, p0.y), pack_h2(p1.x, p1.y));
}

// h_all fp16 linear -> fragment-packed A operand (m16n8k16 layout).
__global__ void __launch_bounds__(256) a_permute_h() {
    int idx = blockIdx.x * blockDim.x + threadIdx.x;
    if (idx >= MTILES*32*32) return;
    int lane = idx & 31;
    int s    = (idx >> 5) & 31;
    int mt   = idx >> 10;            // 0..111
    int g8 = lane >> 2, tq = lane & 3;
    int m0 = mt*16 + g8, m1 = m0 + 8;
    int k0 = s*16 + 2*tq;
    unsigned a0 = 0u, a1 = 0u, a2 = 0u, a3 = 0u;
    if (m0 < BATCH*TT) {
        a0 = *(const unsigned*)(g_hall_h + (size_t)m0*DD + k0);
        a2 = *(const unsigned*)(g_hall_h + (size_t)m0*DD + k0 + 8);
    }
    if (m1 < BATCH*TT) {
        a1 = *(const unsigned*)(g_hall_h + (size_t)m1*DD + k0);
        a3 = *(const unsigned*)(g_hall_h + (size_t)m1*DD + k0 + 8);
    }
    g_hall_p4[idx] = make_uint4(a0, a1, a2, a3);
}

// ---- fused one-time weight transposes (block-range split) -----------------
// blocks [0,1136): transpose_w (ct = b%71, kt = b/71), 71x16 tiles
// blocks [1136,1248): transpose_wdc (jt = bb%16, at = bb/16), 16x7 tiles
__global__ void __launch_bounds__(256) transposes_fused(
    const float* __restrict__ Wh2h, const float* __restrict__ Wh2hr,
    const float* __restrict__ Wdc)
{
    __shared__ float tile[32][33];
    const int b  = blockIdx.x;
    const int tx = threadIdx.x & 31;
    const int ty = threadIdx.x >> 5;   // 0..7

    if (b < 1136) {
        const int ct = b % 71;
        const int kt = b / 71;
        #pragma unroll
        for (int i = 0; i < 4; i++) {
            int col = ct*32 + ty + i*8;
            int k   = kt*32 + tx;
            float v = 0.f;
            if (col < G4)        v = Wh2h[(size_t)col*DD + k];
            else if (col < NCOL) v = Wh2hr[(size_t)(col-G4)*DD + k];
            tile[ty + i*8][tx] = v;
        }
        __syncthreads();
        #pragma unroll
        for (int i = 0; i < 4; i++) {
            int k   = kt*32 + ty + i*8;
            int col = ct*32 + tx;
            g_wt[(size_t)k*WTS + col] = tile[tx][ty + i*8];
        }
    } else {
        const int bb = b - 1136;
        const int jt = bb % 16;
        const int at = bb / 16;
        #pragma unroll
        for (int i = 0; i < 4; i++) {
            int j = jt*32 + ty + i*8;
            int a = at*32 + tx;
            tile[ty + i*8][tx] = (a < AA) ? Wdc[(size_t)j*AA + a] : 0.f;
        }
        __syncthreads();
        #pragma unroll
        for (int i = 0; i < 4; i++) {
            int a = at*32 + ty + i*8;
            int j = jt*32 + tx;
            if (a < AA) g_wdt[(size_t)a*DD + j] = tile[tx][ty + i*8];
        }
    }
}

__device__ __forceinline__ float sigmoidf_(float x) {
    return 1.f / (1.f + expf(-x));
}

// Fence-free semaphores
__device__ __forceinline__ void sem_arrive(unsigned* ctr) {
    __syncthreads();
    if (threadIdx.x == 0)
        asm volatile("red.release.gpu.global.add.u32 [%0], 1;"
                     :: "l"(ctr) : "memory");
}
__device__ __forceinline__ void sem_wait(unsigned* ctr, unsigned tgt) {
    if (threadIdx.x == 0) {
        unsigned v;
        do {
            asm volatile("ld.acquire.gpu.global.u32 %0, [%1];"
                         : "=r"(v) : "l"(ctr) : "memory");
        } while (v < tgt);
    }
    __syncthreads();
}

// ---------------------------------------------------------------------------
// Persistent recurrence kernel — R15 structure; change: w4/wr for step t are
// prefetched BEFORE the arrB wait (step-static data, latency fully hidden).
// ---------------------------------------------------------------------------
__global__ void __launch_bounds__(NTHR, 1) recurrent_kernel(
    const float* __restrict__ bh2h, const float* __restrict__ bh2hr,
    const float* __restrict__ enc,  const float* __restrict__ act)
{
    extern __shared__ float smem[];
    float* hbuf = smem;           // 8192 floats
    float* part = smem + 8192;    // 4096 floats

    const int blk  = blockIdx.x;
    const int tid  = threadIdx.x;
    const int w    = tid >> 5;
    const int lane = tid & 31;

    const int colg  = blk >> 1;
    const int bh    = blk & 1;
    const int col   = colg * 32 + lane;
    const int kbase = w * 64;

    float wreg[64];
    #pragma unroll
    for (int i = 0; i < 64; i++)
        wreg[i] = g_wt[(size_t)(kbase + i) * WTS + col];

    // reduction ownership: p0=tid, p1=tid+256
    float biasv[2];
    float dreg[2];
    const float* w4src[2];   // per-step source pointers (stride known)
    int   w4stride[2];
    #pragma unroll
    for (int pi = 0; pi < 2; pi++) {
        int p  = tid + pi * 256;
        int b  = p >> 5;
        int cg = colg * 32 + (p & 31);
        int batch = bh * 16 + b;
        biasv[pi] = 0.f; dreg[pi] = 0.f;
        w4src[pi] = nullptr; w4stride[pi] = 0;
        if (cg < G4) {
            biasv[pi] = bh2h[cg];
            w4src[pi] = g_w4 + (size_t)(batch*TT) * G4 + cg;
            w4stride[pi] = G4;
        } else if (cg < NCOL) {
            biasv[pi] = bh2hr[cg - G4];
            dreg[pi]  = __ldcg(act + batch * AA + (cg - G4));
            w4src[pi] = g_wr + (size_t)(batch*TT) * AA + (cg - G4);
            w4stride[pi] = AA;
        }
    }

    const bool p2 = (blk < 64);
    const int  colg2 = blk >> 2;
    const int  b2    = (blk & 3) * 8 + w;
    const int  j2    = colg2 * 32 + lane;
    float creg = 0.f;
    if (p2) creg = __ldcg(enc + b2 * DD + j2);

    unsigned* arrA; unsigned* arrB;
    asm("cvta.global.u64 %0, g_arrA;" : "=l"(arrA));
    asm("cvta.global.u64 %0, g_arrB;" : "=l"(arrB));

    for (int t = 0; t < TT; t++) {
        // ---- prefetch step-static w4/wr BEFORE the dependency wait ----
        float w4v[2];
        #pragma unroll
        for (int pi = 0; pi < 2; pi++)
            w4v[pi] = w4src[pi] ? __ldcg(w4src[pi] + (size_t)t * w4stride[pi])
                                : 0.f;

        sem_wait(arrB, 64u * (unsigned)t);

        {
            const float4* src = (const float4*)(g_h + bh * 16 * DD);
            float4* dst = (float4*)hbuf;
            #pragma unroll
            for (int i = 0; i < 8; i++)
                dst[i * NTHR + tid] = __ldcg(src + i * NTHR + tid);
        }
        __syncthreads();

        {
            float acc[16];
            #pragma unroll
            for (int b = 0; b < 16; b++) acc[b] = 0.f;
            const float* hw = hbuf + kbase;
            #pragma unroll
            for (int k4 = 0; k4 < 64; k4 += 4) {
                float w0 = wreg[k4], w1 = wreg[k4+1];
                float w2 = wreg[k4+2], w3 = wreg[k4+3];
                #pragma unroll
                for (int b = 0; b < 16; b++) {
                    float4 hv = *(const float4*)(hw + b * DD + k4);
                    acc[b] += w0*hv.x + w1*hv.y + w2*hv.z + w3*hv.w;
                }
            }
            #pragma unroll
            for (int b = 0; b < 16; b++)
                part[w * 512 + b * 32 + lane] = acc[b];
        }
        __syncthreads();

        #pragma unroll
        for (int pi = 0; pi < 2; pi++) {
            int p  = tid + pi * 256;
            float s = part[p]          + part[p + 512]
                    + part[p + 1024]   + part[p + 1536]
                    + part[p + 2048]   + part[p + 2560]
                    + part[p + 3072]   + part[p + 3584];
            int b  = p >> 5;
            int cg = colg * 32 + (p & 31);
            int batch = bh * 16 + b;
            if (cg < G4) {
                float v = w4v[pi] + s + biasv[pi];
                v = (cg < 3*DD) ? sigmoidf_(v) : tanhf(v);
                g_gates[batch * G4 + cg] = v;
            } else if (cg < NCOL) {
                int acol = cg - G4;
                float r = sigmoidf_(w4v[pi] + s + biasv[pi]);
                dreg[pi] *= r;
                g_dt[batch * AA + acol] = dreg[pi];
            }
        }

        sem_arrive(arrA);

        if (p2) {
            sem_wait(arrA, 142u * (unsigned)(t + 1));

            int bb = (blk & 3) * 8;
            for (int i = tid; i < 8 * AA; i += NTHR)
                part[i] = __ldcg(g_dt + bb * AA + i);
            __syncthreads();

            const float* wdt = g_wdt + j2;
            const float* dts = part + w * AA;
            float acc_a = 0.f, acc_b = 0.f;
            #pragma unroll 10
            for (int a = 0; a < AA; a += 2) {
                acc_a += dts[a    ] * wdt[(a    ) * DD];
                acc_b += dts[a + 1] * wdt[(a + 1) * DD];
            }
            float dtw = tanhf(acc_a + acc_b);
            float gi = __ldcg(g_gates + b2 * G4 + j2);
            float gf = __ldcg(g_gates + b2 * G4 + DD   + j2);
            float go = __ldcg(g_gates + b2 * G4 + 2*DD + j2);
            float ch = __ldcg(g_gates + b2 * G4 + 3*DD + j2);
            creg = gf * creg + gi * ch + dtw;
            float h = go * tanhf(creg);
            g_h[b2 * DD + j2] = h;
            g_hall_h[(size_t)(b2 * TT + t) * DD + j2] = __float2half_rn(h);

            sem_arrive(arrB);
        }
    }
}

// ---------------------------------------------------------------------------
// fp32 tiled GEMM (two small precompute GEMMs)
// ---------------------------------------------------------------------------
#define TS 128
#define KT 8

template<bool GATHER>
__global__ void __launch_bounds__(256) gemm_tn(
    int M, int N, int K,
    const float* __restrict__ A, const int* __restrict__ idx,
    const float* __restrict__ B,
    const float* __restrict__ bias,
    float* __restrict__ C, int ldc)
{
    __shared__ float As[KT][TS];
    __shared__ float Bs[KT][TS];

    int tid = threadIdx.x;
    int lrow = tid >> 1;
    int kc   = (tid & 1) * 4;

    int gm_l = blockIdx.y * TS + lrow;
    int gn_l = blockIdx.x * TS + lrow;

    const float* aptr = nullptr;
    if (gm_l < M) {
        int ar = GATHER ? idx[gm_l] : gm_l;
        aptr = A + (size_t)ar * K;
    }
    const float* bptr = (gn_l < N) ? (B + (size_t)gn_l * K) : nullptr;

    int tx = tid & 15;
    int ty = tid >> 4;

    float acc[8][8];
    #pragma unroll
    for (int i = 0; i < 8; i++)
        #pragma unroll
        for (int j = 0; j < 8; j++) acc[i][j] = 0.f;

    for (int k0 = 0; k0 < K; k0 += KT) {
        float4 av = make_float4(0.f, 0.f, 0.f, 0.f);
        float4 bv = make_float4(0.f, 0.f, 0.f, 0.f);
        if (aptr) av = *(const float4*)(aptr + k0 + kc);
        if (bptr) bv = *(const float4*)(bptr + k0 + kc);
        __syncthreads();
        As[kc+0][lrow] = av.x; As[kc+1][lrow] = av.y;
        As[kc+2][lrow] = av.z; As[kc+3][lrow] = av.w;
        Bs[kc+0][lrow] = bv.x; Bs[kc+1][lrow] = bv.y;
        Bs[kc+2][lrow] = bv.z; Bs[kc+3][lrow] = bv.w;
        __syncthreads();
        #pragma unroll
        for (int kk = 0; kk < KT; kk++) {
            float4 a0 = *(const float4*)&As[kk][ty*8];
            float4 a1 = *(const float4*)&As[kk][ty*8+4];
            float4 b0 = *(const float4*)&Bs[kk][tx*8];
            float4 b1 = *(const float4*)&Bs[kk][tx*8+4];
            float a[8] = {a0.x,a0.y,a0.z,a0.w,a1.x,a1.y,a1.z,a1.w};
            float b[8] = {b0.x,b0.y,b0.z,b0.w,b1.x,b1.y,b1.z,b1.w};
            #pragma unroll
            for (int i = 0; i < 8; i++)
                #pragma unroll
                for (int j = 0; j < 8; j++)
                    acc[i][j] += a[i] * b[j];
        }
    }

    #pragma unroll
    for (int i = 0; i < 8; i++) {
        int gm = blockIdx.y * TS + ty*8 + i;
        if (gm < M) {
            #pragma unroll
            for (int j = 0; j < 8; j += 4) {
                int gn = blockIdx.x * TS + tx*8 + j;
                if (gn < N) {
                    float4 bs = *(const float4*)(bias + gn);
                    float4 o;
                    o.x = acc[i][j+0] + bs.x;
                    o.y = acc[i][j+1] + bs.y;
                    o.z = acc[i][j+2] + bs.z;
                    o.w = acc[i][j+3] + bs.w;
                    *(float4*)(C + (size_t)gm * ldc + gn) = o;
                }
            }
        }
    }
}

// ---------------------------------------------------------------------------
// fp16 fragment-direct output GEMM (m16n8k16, fp32 accumulate) — R15 verbatim.
// ---------------------------------------------------------------------------
__device__ __forceinline__ void mma_fp16(float c[4],
    unsigned a0, unsigned a1, unsigned a2, unsigned a3,
    unsigned b0, unsigned b1)
{
    asm volatile(
        "mma.sync.aligned.m16n8k16.row.col.f32.f16.f16.f32 "
        "{%0,%1,%2,%3}, {%4,%5,%6,%7}, {%8,%9}, {%0,%1,%2,%3};\n"
        : "+f"(c[0]), "+f"(c[1]), "+f"(c[2]), "+f"(c[3])
        : "r"(a0), "r"(a1), "r"(a2), "r"(a3), "r"(b0), "r"(b1));
}

__global__ void __launch_bounds__(256, 1) gemm_fp16(
    int M,
    const float* __restrict__ bias,
    float* __restrict__ C, int ldc)
{
    const int tid  = threadIdx.x;
    const int lane = tid & 31;
    const int w    = tid >> 5;
    const int wmh  = (w & 1);
    const int wnq  = (w >> 1);
    const int g8   = lane >> 2;
    const int tq   = lane & 3;

    const int bMt = blockIdx.y * 8 + wmh * 4;
    const int bNt = blockIdx.x * 32 + wnq * 8;

    const uint4* aBase = g_hall_p4 + (size_t)bMt * 32 * 32 + lane;
    const uint2* bBase = g_wout_p2 + (size_t)bNt * 32 * 32 + lane;

    float acc[4][8][4];
    #pragma unroll
    for (int mi = 0; mi < 4; mi++)
        #pragma unroll
        for (int ni = 0; ni < 8; ni++)
            #pragma unroll
            for (int q = 0; q < 4; q++) acc[mi][ni][q] = 0.f;

    #pragma unroll 1
    for (int kt = 0; kt < 32; kt++) {
        uint2 bf[8];
        #pragma unroll
        for (int ni = 0; ni < 8; ni++)
            bf[ni] = __ldg(bBase + ((size_t)ni * 32 + kt) * 32);
        uint4 af[4];
        #pragma unroll
        for (int mi = 0; mi < 4; mi++)
            af[mi] = __ldg(aBase + ((size_t)mi * 32 + kt) * 32);
        #pragma unroll
        for (int mi = 0; mi < 4; mi++)
            #pragma unroll
            for (int ni = 0; ni < 8; ni++)
                mma_fp16(acc[mi][ni], af[mi].x, af[mi].y, af[mi].z, af[mi].w,
                         bf[ni].x, bf[ni].y);
    }

    #pragma unroll
    for (int mi = 0; mi < 4; mi++) {
        int gm0 = blockIdx.y * 128 + wmh * 64 + mi*16 + g8;
        int gm1 = gm0 + 8;
        #pragma unroll
        for (int ni = 0; ni < 8; ni++) {
            int gn = blockIdx.x * 256 + wnq * 64 + ni*8 + tq*2;
            float2 bs = *(const float2*)(bias + gn);
            if (gm0 < M) {
                float2 o0; o0.x = acc[mi][ni][0] + bs.x; o0.y = acc[mi][ni][1] + bs.y;
                *(float2*)(C + (size_t)gm0 * ldc + gn) = o0;
            }
            if (gm1 < M) {
                float2 o1; o1.x = acc[mi][ni][2] + bs.x; o1.y = acc[mi][ni][3] + bs.y;
                *(float2*)(C + (size_t)gm1 * ldc + gn) = o1;
            }
        }
    }
}

// ---------------------------------------------------------------------------
// Launch  (recurrent_kernel is the 6th launch -> ncu -s 5 -c 1 profiles it)
// ---------------------------------------------------------------------------
extern "C" void kernel_launch(void* const* d_in, const int* in_sizes, int n_in,
                              void* d_out, int out_size) {
    const int*   tgt   = (const int*)  d_in[0];
    const float* enc   = (const float*)d_in[1];
    const float* act   = (const float*)d_in[2];
    const float* E     = (const float*)d_in[3];
    const float* Ww2h  = (const float*)d_in[4];
    const float* bw2h  = (const float*)d_in[5];
    const float* Wh2h  = (const float*)d_in[6];
    const float* bh2h  = (const float*)d_in[7];
    const float* Ww2hr = (const float*)d_in[8];
    const float* bw2hr = (const float*)d_in[9];
    const float* Wh2hr = (const float*)d_in[10];
    const float* bh2hr = (const float*)d_in[11];
    const float* Wdc   = (const float*)d_in[12];
    const float* Wout  = (const float*)d_in[13];
    const float* bout  = (const float*)d_in[14];
    float* out = (float*)d_out;

    float *pw4, *pwr;
    cudaGetSymbolAddress((void**)&pw4, g_w4);
    cudaGetSymbolAddress((void**)&pwr, g_wr);

    // 1: state init
    init_kernel<<<(BATCH*DD + 255) / 256, 256>>>(enc);

    // 2: fused one-time weight transposes
    transposes_fused<<<1136 + 112, 256>>>(Wh2h, Wh2hr, Wdc);

    // 3: W_out -> fp16 fragment-packed
    wout_permute_h<<<(VV/8)*32*32 / 256, 256>>>(Wout);

    // 4,5: precompute w4_all and wr_all
    {
        dim3 g1((G4 + TS - 1) / TS, (BATCH*TT + TS - 1) / TS);
        gemm_tn<true><<<g1, 256>>>(BATCH*TT, G4, DW, E, tgt, Ww2h, bw2h, pw4, G4);
        dim3 g2((AA + TS - 1) / TS, (BATCH*TT + TS - 1) / TS);
        gemm_tn<true><<<g2, 256>>>(BATCH*TT, AA, DW, E, tgt, Ww2hr, bw2hr, pwr, AA);
    }

    // 6: recurrence (ncu -s 5 profiles this launch)
    recurrent_kernel<<<NBLK, NTHR, 48*1024>>>(bh2h, bh2hr, enc, act);

    // 7: h_all -> fp16 fragment-packed
    a_permute_h<<<(MTILES*32*32 + 255) / 256, 256>>>();

    // 8: fp16 tensor-core output projection
    {
        dim3 g3(VV / 256, (BATCH*TT + 127) / 128);   // 125 x 14
        gemm_fp16<<<g3, 256>>>(BATCH*TT, bout, out, VV);
    }
}

// round 17
// speedup vs baseline: 1.2440x; 1.0334x over previous
#include <cuda_runtime.h>
#include <cuda_fp16.h>
#include <math.h>

// Problem constants
#define BATCH 32
#define TT 55
#define VV 32000
#define DW 256
#define DD 512
#define AA 200
#define G4 2048   // 4*D
#define NCOL (G4 + AA)   // 2248
#define WTS 2304         // padded row stride of transposed weights

#define NBLK 142   // recurrence blocks
#define NTHR 256

#define MTILES 112       // padded m16-tile count (ceil(1760/16)=110 -> 112)

// Scratch (device globals; no allocation allowed)
__device__ float    g_w4[BATCH*TT*G4];
__device__ float    g_wr[BATCH*TT*AA];
__device__ float    g_h[BATCH*DD];
__device__ float    g_dt[BATCH*AA];
__device__ float    g_gates[BATCH*G4];
__device__ __half   g_hall_h[BATCH*TT*DD];    // h_all fp16, linear [m][k]
__device__ uint2    g_wout_p2[(VV/8)*32*32];  // W_out fp16 fragment-packed (32MB)
__device__ uint4    g_hall_p4[MTILES*32*32];  // h_all fp16 fragment-packed
__device__ float    g_wt[DD*WTS];             // [Wh2h;Wh2hr] transposed [k][col]
__device__ float    g_wdt[AA*DD];             // Wdc transposed [a][j]
__device__ unsigned g_arrA;
__device__ unsigned g_arrB;

// ---------------------------------------------------------------------------
__global__ void init_kernel(const float* __restrict__ enc) {
    int i = blockIdx.x * blockDim.x + threadIdx.x;
    if (i < BATCH*DD) g_h[i] = enc[i];
    if (i == 0) { g_arrA = 0u; g_arrB = 0u; }
}

__device__ __forceinline__ unsigned pack_h2(float a, float b) {
    unsigned lo = __half_as_ushort(__float2half_rn(a));
    unsigned hi = __half_as_ushort(__float2half_rn(b));
    return lo | (hi << 16);
}

// W_out -> fp16 fragment-packed B operand (m16n8k16 layout).
__global__ void __launch_bounds__(256) wout_permute_h(const float* __restrict__ W) {
    int idx = blockIdx.x * blockDim.x + threadIdx.x;
    int lane = idx & 31;
    int s    = (idx >> 5) & 31;
    int nt   = idx >> 10;            // 0..3999
    int g8 = lane >> 2, tq = lane & 3;
    const float* row = W + (size_t)(nt*8 + g8) * DD + s*16;
    float2 p0 = *(const float2*)(row + 2*tq);
    float2 p1 = *(const float2*)(row + 2*tq + 8);
    g_wout_p2[idx] = make_uint2(pack_h2(p0.x, p0.y), pack_h2(p1.x, p1.y));
}

// h_all fp16 linear -> fragment-packed A operand (m16n8k16 layout).
__global__ void __launch_bounds__(256) a_permute_h() {
    int idx = blockIdx.x * blockDim.x + threadIdx.x;
    if (idx >= MTILES*32*32) return;
    int lane = idx & 31;
    int s    = (idx >> 5) & 31;
    int mt   = idx >> 10;            // 0..111
    int g8 = lane >> 2, tq = lane & 3;
    int m0 = mt*16 + g8, m1 = m0 + 8;
    int k0 = s*16 + 2*tq;
    unsigned a0 = 0u, a1 = 0u, a2 = 0u, a3 = 0u;
    if (m0 < BATCH*TT) {
        a0 = *(const unsigned*)(g_hall_h + (size_t)m0*DD + k0);
        a2 = *(const unsigned*)(g_hall_h + (size_t)m0*DD + k0 + 8);
    }
    if (m1 < BATCH*TT) {
        a1 = *(const unsigned*)(g_hall_h + (size_t)m1*DD + k0);
        a3 = *(const unsigned*)(g_hall_h + (size_t)m1*DD + k0 + 8);
    }
    g_hall_p4[idx] = make_uint4(a0, a1, a2, a3);
}

// ---- fused one-time weight transposes (block-range split) -----------------
__global__ void __launch_bounds__(256) transposes_fused(
    const float* __restrict__ Wh2h, const float* __restrict__ Wh2hr,
    const float* __restrict__ Wdc)
{
    __shared__ float tile[32][33];
    const int b  = blockIdx.x;
    const int tx = threadIdx.x & 31;
    const int ty = threadIdx.x >> 5;   // 0..7

    if (b < 1136) {
        const int ct = b % 71;
        const int kt = b / 71;
        #pragma unroll
        for (int i = 0; i < 4; i++) {
            int col = ct*32 + ty + i*8;
            int k   = kt*32 + tx;
            float v = 0.f;
            if (col < G4)        v = Wh2h[(size_t)col*DD + k];
            else if (col < NCOL) v = Wh2hr[(size_t)(col-G4)*DD + k];
            tile[ty + i*8][tx] = v;
        }
        __syncthreads();
        #pragma unroll
        for (int i = 0; i < 4; i++) {
            int k   = kt*32 + ty + i*8;
            int col = ct*32 + tx;
            g_wt[(size_t)k*WTS + col] = tile[tx][ty + i*8];
        }
    } else {
        const int bb = b - 1136;
        const int jt = bb % 16;
        const int at = bb / 16;
        #pragma unroll
        for (int i = 0; i < 4; i++) {
            int j = jt*32 + ty + i*8;
            int a = at*32 + tx;
            tile[ty + i*8][tx] = (a < AA) ? Wdc[(size_t)j*AA + a] : 0.f;
        }
        __syncthreads();
        #pragma unroll
        for (int i = 0; i < 4; i++) {
            int a = at*32 + ty + i*8;
            int j = jt*32 + tx;
            if (a < AA) g_wdt[(size_t)a*DD + j] = tile[tx][ty + i*8];
        }
    }
}

__device__ __forceinline__ float sigmoidf_(float x) {
    return 1.f / (1.f + expf(-x));
}

// Fence-free semaphores
__device__ __forceinline__ void sem_arrive(unsigned* ctr) {
    __syncthreads();
    if (threadIdx.x == 0)
        asm volatile("red.release.gpu.global.add.u32 [%0], 1;"
                     :: "l"(ctr) : "memory");
}
__device__ __forceinline__ void sem_wait(unsigned* ctr, unsigned tgt) {
    if (threadIdx.x == 0) {
        unsigned v;
        do {
            asm volatile("ld.acquire.gpu.global.u32 %0, [%1];"
                         : "=r"(v) : "l"(ctr) : "memory");
        } while (v < tgt);
    }
    __syncthreads();
}

// ---------------------------------------------------------------------------
// Persistent recurrence kernel — R16 structure; phase2 gate loads hoisted
// above the dt dot product (latency hidden behind 100 FFMA iterations).
// ---------------------------------------------------------------------------
__global__ void __launch_bounds__(NTHR, 1) recurrent_kernel(
    const float* __restrict__ bh2h, const float* __restrict__ bh2hr,
    const float* __restrict__ enc,  const float* __restrict__ act)
{
    extern __shared__ float smem[];
    float* hbuf = smem;           // 8192 floats
    float* part = smem + 8192;    // 4096 floats

    const int blk  = blockIdx.x;
    const int tid  = threadIdx.x;
    const int w    = tid >> 5;
    const int lane = tid & 31;

    const int colg  = blk >> 1;
    const int bh    = blk & 1;
    const int col   = colg * 32 + lane;
    const int kbase = w * 64;

    float wreg[64];
    #pragma unroll
    for (int i = 0; i < 64; i++)
        wreg[i] = g_wt[(size_t)(kbase + i) * WTS + col];

    float biasv[2];
    float dreg[2];
    const float* w4src[2];
    int   w4stride[2];
    #pragma unroll
    for (int pi = 0; pi < 2; pi++) {
        int p  = tid + pi * 256;
        int b  = p >> 5;
        int cg = colg * 32 + (p & 31);
        int batch = bh * 16 + b;
        biasv[pi] = 0.f; dreg[pi] = 0.f;
        w4src[pi] = nullptr; w4stride[pi] = 0;
        if (cg < G4) {
            biasv[pi] = bh2h[cg];
            w4src[pi] = g_w4 + (size_t)(batch*TT) * G4 + cg;
            w4stride[pi] = G4;
        } else if (cg < NCOL) {
            biasv[pi] = bh2hr[cg - G4];
            dreg[pi]  = __ldcg(act + batch * AA + (cg - G4));
            w4src[pi] = g_wr + (size_t)(batch*TT) * AA + (cg - G4);
            w4stride[pi] = AA;
        }
    }

    const bool p2 = (blk < 64);
    const int  colg2 = blk >> 2;
    const int  b2    = (blk & 3) * 8 + w;
    const int  j2    = colg2 * 32 + lane;
    float creg = 0.f;
    if (p2) creg = __ldcg(enc + b2 * DD + j2);

    unsigned* arrA; unsigned* arrB;
    asm("cvta.global.u64 %0, g_arrA;" : "=l"(arrA));
    asm("cvta.global.u64 %0, g_arrB;" : "=l"(arrB));

    for (int t = 0; t < TT; t++) {
        // prefetch step-static w4/wr BEFORE the dependency wait
        float w4v[2];
        #pragma unroll
        for (int pi = 0; pi < 2; pi++)
            w4v[pi] = w4src[pi] ? __ldcg(w4src[pi] + (size_t)t * w4stride[pi])
                                : 0.f;

        sem_wait(arrB, 64u * (unsigned)t);

        {
            const float4* src = (const float4*)(g_h + bh * 16 * DD);
            float4* dst = (float4*)hbuf;
            #pragma unroll
            for (int i = 0; i < 8; i++)
                dst[i * NTHR + tid] = __ldcg(src + i * NTHR + tid);
        }
        __syncthreads();

        {
            float acc[16];
            #pragma unroll
            for (int b = 0; b < 16; b++) acc[b] = 0.f;
            const float* hw = hbuf + kbase;
            #pragma unroll
            for (int k4 = 0; k4 < 64; k4 += 4) {
                float w0 = wreg[k4], w1 = wreg[k4+1];
                float w2 = wreg[k4+2], w3 = wreg[k4+3];
                #pragma unroll
                for (int b = 0; b < 16; b++) {
                    float4 hv = *(const float4*)(hw + b * DD + k4);
                    acc[b] += w0*hv.x + w1*hv.y + w2*hv.z + w3*hv.w;
                }
            }
            #pragma unroll
            for (int b = 0; b < 16; b++)
                part[w * 512 + b * 32 + lane] = acc[b];
        }
        __syncthreads();

        #pragma unroll
        for (int pi = 0; pi < 2; pi++) {
            int p  = tid + pi * 256;
            float s = part[p]          + part[p + 512]
                    + part[p + 1024]   + part[p + 1536]
                    + part[p + 2048]   + part[p + 2560]
                    + part[p + 3072]   + part[p + 3584];
            int b  = p >> 5;
            int cg = colg * 32 + (p & 31);
            int batch = bh * 16 + b;
            if (cg < G4) {
                float v = w4v[pi] + s + biasv[pi];
                v = (cg < 3*DD) ? sigmoidf_(v) : tanhf(v);
                g_gates[batch * G4 + cg] = v;
            } else if (cg < NCOL) {
                int acol = cg - G4;
                float r = sigmoidf_(w4v[pi] + s + biasv[pi]);
                dreg[pi] *= r;
                g_dt[batch * AA + acol] = dreg[pi];
            }
        }

        sem_arrive(arrA);

        if (p2) {
            sem_wait(arrA, 142u * (unsigned)(t + 1));

            // hoist gate loads: issue before the dt dot (latency overlapped)
            float gi = __ldcg(g_gates + b2 * G4 + j2);
            float gf = __ldcg(g_gates + b2 * G4 + DD   + j2);
            float go = __ldcg(g_gates + b2 * G4 + 2*DD + j2);
            float ch = __ldcg(g_gates + b2 * G4 + 3*DD + j2);

            int bb = (blk & 3) * 8;
            for (int i = tid; i < 8 * AA; i += NTHR)
                part[i] = __ldcg(g_dt + bb * AA + i);
            __syncthreads();

            const float* wdt = g_wdt + j2;
            const float* dts = part + w * AA;
            float acc_a = 0.f, acc_b = 0.f;
            #pragma unroll 10
            for (int a = 0; a < AA; a += 2) {
                acc_a += dts[a    ] * wdt[(a    ) * DD];
                acc_b += dts[a + 1] * wdt[(a + 1) * DD];
            }
            float dtw = tanhf(acc_a + acc_b);
            creg = gf * creg + gi * ch + dtw;
            float h = go * tanhf(creg);
            g_h[b2 * DD + j2] = h;
            g_hall_h[(size_t)(b2 * TT + t) * DD + j2] = __float2half_rn(h);

            sem_arrive(arrB);
        }
    }
}

// ---------------------------------------------------------------------------
// fp32 tiled GEMM (two small precompute GEMMs)
// ---------------------------------------------------------------------------
#define TS 128
#define KT 8

template<bool GATHER>
__global__ void __launch_bounds__(256) gemm_tn(
    int M, int N, int K,
    const float* __restrict__ A, const int* __restrict__ idx,
    const float* __restrict__ B,
    const float* __restrict__ bias,
    float* __restrict__ C, int ldc)
{
    __shared__ float As[KT][TS];
    __shared__ float Bs[KT][TS];

    int tid = threadIdx.x;
    int lrow = tid >> 1;
    int kc   = (tid & 1) * 4;

    int gm_l = blockIdx.y * TS + lrow;
    int gn_l = blockIdx.x * TS + lrow;

    const float* aptr = nullptr;
    if (gm_l < M) {
        int ar = GATHER ? idx[gm_l] : gm_l;
        aptr = A + (size_t)ar * K;
    }
    const float* bptr = (gn_l < N) ? (B + (size_t)gn_l * K) : nullptr;

    int tx = tid & 15;
    int ty = tid >> 4;

    float acc[8][8];
    #pragma unroll
    for (int i = 0; i < 8; i++)
        #pragma unroll
        for (int j = 0; j < 8; j++) acc[i][j] = 0.f;

    for (int k0 = 0; k0 < K; k0 += KT) {
        float4 av = make_float4(0.f, 0.f, 0.f, 0.f);
        float4 bv = make_float4(0.f, 0.f, 0.f, 0.f);
        if (aptr) av = *(const float4*)(aptr + k0 + kc);
        if (bptr) bv = *(const float4*)(bptr + k0 + kc);
        __syncthreads();
        As[kc+0][lrow] = av.x; As[kc+1][lrow] = av.y;
        As[kc+2][lrow] = av.z; As[kc+3][lrow] = av.w;
        Bs[kc+0][lrow] = bv.x; Bs[kc+1][lrow] = bv.y;
        Bs[kc+2][lrow] = bv.z; Bs[kc+3][lrow] = bv.w;
        __syncthreads();
        #pragma unroll
        for (int kk = 0; kk < KT; kk++) {
            float4 a0 = *(const float4*)&As[kk][ty*8];
            float4 a1 = *(const float4*)&As[kk][ty*8+4];
            float4 b0 = *(const float4*)&Bs[kk][tx*8];
            float4 b1 = *(const float4*)&Bs[kk][tx*8+4];
            float a[8] = {a0.x,a0.y,a0.z,a0.w,a1.x,a1.y,a1.z,a1.w};
            float b[8] = {b0.x,b0.y,b0.z,b0.w,b1.x,b1.y,b1.z,b1.w};
            #pragma unroll
            for (int i = 0; i < 8; i++)
                #pragma unroll
                for (int j = 0; j < 8; j++)
                    acc[i][j] += a[i] * b[j];
        }
    }

    #pragma unroll
    for (int i = 0; i < 8; i++) {
        int gm = blockIdx.y * TS + ty*8 + i;
        if (gm < M) {
            #pragma unroll
            for (int j = 0; j < 8; j += 4) {
                int gn = blockIdx.x * TS + tx*8 + j;
                if (gn < N) {
                    float4 bs = *(const float4*)(bias + gn);
                    float4 o;
                    o.x = acc[i][j+0] + bs.x;
                    o.y = acc[i][j+1] + bs.y;
                    o.z = acc[i][j+2] + bs.z;
                    o.w = acc[i][j+3] + bs.w;
                    *(float4*)(C + (size_t)gm * ldc + gn) = o;
                }
            }
        }
    }
}

// ---------------------------------------------------------------------------
// fp16 fragment-direct output GEMM (m16n8k16, fp32 accumulate).
// v2: CTA 128x128, warp tile 64x32 -> ~110 regs -> 2 CTAs/SM (occupancy
// experiment: latency-bound hypothesis). Grid 250x14.
// ---------------------------------------------------------------------------
__device__ __forceinline__ void mma_fp16(float c[4],
    unsigned a0, unsigned a1, unsigned a2, unsigned a3,
    unsigned b0, unsigned b1)
{
    asm volatile(
        "mma.sync.aligned.m16n8k16.row.col.f32.f16.f16.f32 "
        "{%0,%1,%2,%3}, {%4,%5,%6,%7}, {%8,%9}, {%0,%1,%2,%3};\n"
        : "+f"(c[0]), "+f"(c[1]), "+f"(c[2]), "+f"(c[3])
        : "r"(a0), "r"(a1), "r"(a2), "r"(a3), "r"(b0), "r"(b1));
}

__global__ void __launch_bounds__(256, 2) gemm_fp16(
    int M,
    const float* __restrict__ bias,
    float* __restrict__ C, int ldc)
{
    const int tid  = threadIdx.x;
    const int lane = tid & 31;
    const int w    = tid >> 5;
    const int wmh  = (w & 1);            // m half (64 rows)
    const int wnq  = (w >> 1);           // n quarter (32 cols)
    const int g8   = lane >> 2;
    const int tq   = lane & 3;

    const int bMt = blockIdx.y * 8 + wmh * 4;    // 4 m16-tiles per warp
    const int bNt = blockIdx.x * 16 + wnq * 4;   // 4 n8-tiles per warp

    const uint4* aBase = g_hall_p4 + (size_t)bMt * 32 * 32 + lane;
    const uint2* bBase = g_wout_p2 + (size_t)bNt * 32 * 32 + lane;

    float acc[4][4][4];
    #pragma unroll
    for (int mi = 0; mi < 4; mi++)
        #pragma unroll
        for (int ni = 0; ni < 4; ni++)
            #pragma unroll
            for (int q = 0; q < 4; q++) acc[mi][ni][q] = 0.f;

    #pragma unroll 1
    for (int kt = 0; kt < 32; kt++) {     // 32 k16-tiles over K=512
        uint2 bf[4];
        #pragma unroll
        for (int ni = 0; ni < 4; ni++)
            bf[ni] = __ldg(bBase + ((size_t)ni * 32 + kt) * 32);
        uint4 af[4];
        #pragma unroll
        for (int mi = 0; mi < 4; mi++)
            af[mi] = __ldg(aBase + ((size_t)mi * 32 + kt) * 32);
        #pragma unroll
        for (int mi = 0; mi < 4; mi++)
            #pragma unroll
            for (int ni = 0; ni < 4; ni++)
                mma_fp16(acc[mi][ni], af[mi].x, af[mi].y, af[mi].z, af[mi].w,
                         bf[ni].x, bf[ni].y);
    }

    // epilogue: C frag m16n8: (c0,c1) row g8 cols 2tq,2tq+1; (c2,c3) row g8+8
    #pragma unroll
    for (int mi = 0; mi < 4; mi++) {
        int gm0 = blockIdx.y * 128 + wmh * 64 + mi*16 + g8;
        int gm1 = gm0 + 8;
        #pragma unroll
        for (int ni = 0; ni < 4; ni++) {
            int gn = blockIdx.x * 128 + wnq * 32 + ni*8 + tq*2;
            float2 bs = *(const float2*)(bias + gn);
            if (gm0 < M) {
                float2 o0; o0.x = acc[mi][ni][0] + bs.x; o0.y = acc[mi][ni][1] + bs.y;
                *(float2*)(C + (size_t)gm0 * ldc + gn) = o0;
            }
            if (gm1 < M) {
                float2 o1; o1.x = acc[mi][ni][2] + bs.x; o1.y = acc[mi][ni][3] + bs.y;
                *(float2*)(C + (size_t)gm1 * ldc + gn) = o1;
            }
        }
    }
}

// ---------------------------------------------------------------------------
// Launch
// ---------------------------------------------------------------------------
extern "C" void kernel_launch(void* const* d_in, const int* in_sizes, int n_in,
                              void* d_out, int out_size) {
    const int*   tgt   = (const int*)  d_in[0];
    const float* enc   = (const float*)d_in[1];
    const float* act   = (const float*)d_in[2];
    const float* E     = (const float*)d_in[3];
    const float* Ww2h  = (const float*)d_in[4];
    const float* bw2h  = (const float*)d_in[5];
    const float* Wh2h  = (const float*)d_in[6];
    const float* bh2h  = (const float*)d_in[7];
    const float* Ww2hr = (const float*)d_in[8];
    const float* bw2hr = (const float*)d_in[9];
    const float* Wh2hr = (const float*)d_in[10];
    const float* bh2hr = (const float*)d_in[11];
    const float* Wdc   = (const float*)d_in[12];
    const float* Wout  = (const float*)d_in[13];
    const float* bout  = (const float*)d_in[14];
    float* out = (float*)d_out;

    float *pw4, *pwr;
    cudaGetSymbolAddress((void**)&pw4, g_w4);
    cudaGetSymbolAddress((void**)&pwr, g_wr);

    // 1: state init
    init_kernel<<<(BATCH*DD + 255) / 256, 256>>>(enc);

    // 2: fused one-time weight transposes
    transposes_fused<<<1136 + 112, 256>>>(Wh2h, Wh2hr, Wdc);

    // 3: W_out -> fp16 fragment-packed
    wout_permute_h<<<(VV/8)*32*32 / 256, 256>>>(Wout);

    // 4,5: precompute w4_all and wr_all
    {
        dim3 g1((G4 + TS - 1) / TS, (BATCH*TT + TS - 1) / TS);
        gemm_tn<true><<<g1, 256>>>(BATCH*TT, G4, DW, E, tgt, Ww2h, bw2h, pw4, G4);
        dim3 g2((AA + TS - 1) / TS, (BATCH*TT + TS - 1) / TS);
        gemm_tn<true><<<g2, 256>>>(BATCH*TT, AA, DW, E, tgt, Ww2hr, bw2hr, pwr, AA);
    }

    // 6: recurrence
    recurrent_kernel<<<NBLK, NTHR, 48*1024>>>(bh2h, bh2hr, enc, act);

    // 7: h_all -> fp16 fragment-packed
    a_permute_h<<<(MTILES*32*32 + 255) / 256, 256>>>();

    // 8: fp16 tensor-core output projection (occupancy-2 config)
    {
        dim3 g3(VV / 128, (BATCH*TT + 127) / 128);   // 250 x 14
        gemm_fp16<<<g3, 256>>>(BATCH*TT, bout, out, VV);
    }
}